// round 1
// baseline (speedup 1.0000x reference)
#include <cuda_runtime.h>
#include <cstdint>
#include <math.h>

#define BB 512
#define TT 180
#define NM 40
#define HH 768
#define GG 3072   // 4*HH
#define PR 256

// ---- static device scratch (allocation-free rule) ----
__device__ float g_xg[283115520];          // [T][B][G]  = 180*512*3072
__device__ float g_hseq0[70778880];        // [B][T][H]
__device__ float g_hseq1[70778880];        // [B][T][H]
__device__ float g_hbuf[2 * BB * HH];      // h ping-pong
__device__ float g_c[BB * HH];             // cell state

__device__ __forceinline__ uint32_t f2tf(float f) {
    uint32_t u;
    asm("cvt.rna.tf32.f32 %0, %1;" : "=r"(u) : "f"(f));
    return u;
}

__device__ __forceinline__ void mma8(float* d, uint32_t a0, uint32_t a1, uint32_t a2, uint32_t a3,
                                     uint32_t b0, uint32_t b1) {
    asm volatile(
        "mma.sync.aligned.m16n8k8.row.col.f32.tf32.tf32.f32 "
        "{%0,%1,%2,%3}, {%4,%5,%6,%7}, {%8,%9}, {%0,%1,%2,%3};\n"
        : "+f"(d[0]), "+f"(d[1]), "+f"(d[2]), "+f"(d[3])
        : "r"(a0), "r"(a1), "r"(a2), "r"(a3), "r"(b0), "r"(b1));
}

__device__ __forceinline__ float sigf(float x) { return 1.f / (1.f + expf(-x)); }

// ---------------------------------------------------------------------------
// zero h0 and c
// ---------------------------------------------------------------------------
__global__ void zero2_kernel(float* a, float* b, int n) {
    int i = blockIdx.x * blockDim.x + threadIdx.x;
    if (i < n) { a[i] = 0.f; b[i] = 0.f; }
}

// ---------------------------------------------------------------------------
// Input GEMM: out[t][b][n] = bias[n] + sum_k A[b*T+t][k] * W[n][k]
// A: [M=B*T, K] row-major. W: [G, K] row-major. out: [T][B][G].
// CTA: 64(M) x 64(N), 8 warps (4x2), KC=16 double-buffered, tf32 MMA.
// ---------------------------------------------------------------------------
__global__ __launch_bounds__(256) void gemm_in_kernel(
    const float* __restrict__ A, const float* __restrict__ W,
    const float* __restrict__ b_ih, const float* __restrict__ b_hh,
    float* __restrict__ out, int K)
{
    __shared__ uint32_t As[2][64][17];
    __shared__ uint32_t Bs[2][64][17];

    const int tid = threadIdx.x;
    const int wid = tid >> 5, lane = tid & 31;
    const int wm = wid >> 1, wn = wid & 1;
    const int g = lane >> 2, tg = lane & 3;
    const int m0 = blockIdx.x * 64, n0 = blockIdx.y * 64;

    float acc[4][4];
    #pragma unroll
    for (int i = 0; i < 4; i++)
        #pragma unroll
        for (int j = 0; j < 4; j++) acc[i][j] = 0.f;

    const int nch = (K + 15) / 16;

    auto load = [&](int buf, int kc) {
        int k0 = kc * 16;
        #pragma unroll
        for (int i = tid; i < 64 * 16; i += 256) {
            int r = i >> 4, k = i & 15;
            int gk = k0 + k;
            float av = (gk < K) ? A[(size_t)(m0 + r) * K + gk] : 0.f;
            float wv = (gk < K) ? W[(size_t)(n0 + r) * K + gk] : 0.f;
            As[buf][r][k] = f2tf(av);
            Bs[buf][r][k] = f2tf(wv);
        }
    };

    load(0, 0);
    __syncthreads();

    for (int kc = 0; kc < nch; kc++) {
        int cur = kc & 1, nxt = cur ^ 1;
        if (kc + 1 < nch) load(nxt, kc + 1);
        #pragma unroll
        for (int k8 = 0; k8 < 2; k8++) {
            uint32_t a0 = As[cur][wm * 16 + g][k8 * 8 + tg];
            uint32_t a1 = As[cur][wm * 16 + g + 8][k8 * 8 + tg];
            uint32_t a2 = As[cur][wm * 16 + g][k8 * 8 + tg + 4];
            uint32_t a3 = As[cur][wm * 16 + g + 8][k8 * 8 + tg + 4];
            #pragma unroll
            for (int nt = 0; nt < 4; nt++) {
                uint32_t b0 = Bs[cur][wn * 32 + nt * 8 + g][k8 * 8 + tg];
                uint32_t b1 = Bs[cur][wn * 32 + nt * 8 + g][k8 * 8 + tg + 4];
                mma8(acc[nt], a0, a1, a2, a3, b0, b1);
            }
        }
        __syncthreads();
    }

    // epilogue: add bias, scatter rows to [T][B][G]
    #pragma unroll
    for (int nt = 0; nt < 4; nt++) {
        #pragma unroll
        for (int r2 = 0; r2 < 4; r2++) {
            int row = wm * 16 + g + ((r2 & 2) ? 8 : 0);
            int m = m0 + row;
            int col = n0 + wn * 32 + nt * 8 + 2 * tg + (r2 & 1);
            int b = m / TT, t = m % TT;
            out[((size_t)t * BB + b) * GG + col] = acc[nt][r2] + b_ih[col] + b_hh[col];
        }
    }
}

// ---------------------------------------------------------------------------
// Fused LSTM step: gates = xg[t] + h_in @ W_hh^T, then pointwise c/h update.
// CTA: 64 batch rows x 64 hidden cols (x 4 gates = 256 gate columns).
// Grid: (512/64, 768/64) = (8, 12).
// ---------------------------------------------------------------------------
__global__ __launch_bounds__(256) void lstm_step_kernel(
    const float* __restrict__ Whh, const float* __restrict__ xg,
    const float* __restrict__ h_in, float* __restrict__ h_out,
    float* __restrict__ c_st, float* __restrict__ hseq_out, int t)
{
    __shared__ uint32_t As[2][64][17];    // h tile [batch][k]
    __shared__ uint32_t Bs[2][256][17];   // w tile [4*64 gate cols][k]

    const int tid = threadIdx.x;
    const int wid = tid >> 5, lane = tid & 31;
    const int wm = wid >> 1, wn = wid & 1;
    const int g = lane >> 2, tg = lane & 3;
    const int m0 = blockIdx.x * 64;   // batch base
    const int j0 = blockIdx.y * 64;   // hidden-col base

    float acc[4][4][4];  // [gate][ntile][reg]
    #pragma unroll
    for (int a = 0; a < 4; a++)
        #pragma unroll
        for (int b = 0; b < 4; b++)
            #pragma unroll
            for (int c = 0; c < 4; c++) acc[a][b][c] = 0.f;

    auto loadA = [&](int buf, int kc) {
        int k0 = kc * 16;
        #pragma unroll
        for (int i = tid; i < 64 * 16; i += 256) {
            int r = i >> 4, k = i & 15;
            As[buf][r][k] = f2tf(h_in[(size_t)(m0 + r) * HH + k0 + k]);
        }
    };
    auto loadB = [&](int buf, int kc) {
        int k0 = kc * 16;
        #pragma unroll
        for (int i = tid; i < 256 * 16; i += 256) {
            int nr = i >> 4, k = i & 15;
            int gate = nr >> 6, jj = nr & 63;
            Bs[buf][nr][k] = f2tf(Whh[(size_t)(gate * HH + j0 + jj) * HH + k0 + k]);
        }
    };

    loadA(0, 0);
    loadB(0, 0);
    __syncthreads();

    const int nch = HH / 16;  // 48
    for (int kc = 0; kc < nch; kc++) {
        int cur = kc & 1, nxt = cur ^ 1;
        if (kc + 1 < nch) { loadA(nxt, kc + 1); loadB(nxt, kc + 1); }
        #pragma unroll
        for (int k8 = 0; k8 < 2; k8++) {
            uint32_t a0 = As[cur][wm * 16 + g][k8 * 8 + tg];
            uint32_t a1 = As[cur][wm * 16 + g + 8][k8 * 8 + tg];
            uint32_t a2 = As[cur][wm * 16 + g][k8 * 8 + tg + 4];
            uint32_t a3 = As[cur][wm * 16 + g + 8][k8 * 8 + tg + 4];
            #pragma unroll
            for (int gate = 0; gate < 4; gate++) {
                #pragma unroll
                for (int nt = 0; nt < 4; nt++) {
                    int brow = gate * 64 + wn * 32 + nt * 8 + g;
                    uint32_t b0 = Bs[cur][brow][k8 * 8 + tg];
                    uint32_t b1 = Bs[cur][brow][k8 * 8 + tg + 4];
                    mma8(acc[gate][nt], a0, a1, a2, a3, b0, b1);
                }
            }
        }
        __syncthreads();
    }

    // pointwise epilogue
    #pragma unroll
    for (int nt = 0; nt < 4; nt++) {
        #pragma unroll
        for (int r2 = 0; r2 < 4; r2++) {
            int row = wm * 16 + g + ((r2 & 2) ? 8 : 0);
            int b = m0 + row;
            int j = j0 + wn * 32 + nt * 8 + 2 * tg + (r2 & 1);
            size_t xbase = ((size_t)t * BB + b) * GG;
            float pi = acc[0][nt][r2] + xg[xbase + 0 * HH + j];
            float pf = acc[1][nt][r2] + xg[xbase + 1 * HH + j];
            float pg = acc[2][nt][r2] + xg[xbase + 2 * HH + j];
            float po = acc[3][nt][r2] + xg[xbase + 3 * HH + j];
            float iv = sigf(pi);
            float fv = sigf(pf);
            float gv = tanhf(pg);
            float ov = sigf(po);
            size_t cix = (size_t)b * HH + j;
            float cn = fv * c_st[cix] + iv * gv;
            c_st[cix] = cn;
            float hn = ov * tanhf(cn);
            h_out[cix] = hn;
            hseq_out[((size_t)b * TT + t) * HH + j] = hn;
        }
    }
}

// ---------------------------------------------------------------------------
// Projection + L2 normalize: out[b][o] = (h[b]·pw[o] + pb[o]) / ||e_b||
// Block handles 8 batch rows; 256 threads = 256 output dims.
// ---------------------------------------------------------------------------
__global__ __launch_bounds__(256) void proj_kernel(
    const float* __restrict__ h, const float* __restrict__ pw,
    const float* __restrict__ pb, float* __restrict__ out)
{
    __shared__ float hs[8][HH];
    __shared__ float red[256];
    const int b0 = blockIdx.x * 8;
    const int tid = threadIdx.x;

    for (int i = tid; i < 8 * HH; i += 256) {
        int r = i / HH, k = i % HH;
        hs[r][k] = h[(size_t)(b0 + r) * HH + k];
    }
    __syncthreads();

    float s[8];
    float bias = pb[tid];
    #pragma unroll
    for (int r = 0; r < 8; r++) s[r] = bias;
    const float* w = pw + (size_t)tid * HH;
    for (int k = 0; k < HH; k++) {
        float wv = w[k];
        #pragma unroll
        for (int r = 0; r < 8; r++) s[r] += wv * hs[r][k];
    }

    for (int r = 0; r < 8; r++) {
        red[tid] = s[r] * s[r];
        __syncthreads();
        for (int off = 128; off > 0; off >>= 1) {
            if (tid < off) red[tid] += red[tid + off];
            __syncthreads();
        }
        float rn = rsqrtf(red[0]);
        __syncthreads();
        out[(size_t)(b0 + r) * PR + tid] = s[r] * rn;
    }
}

// ---------------------------------------------------------------------------
// host
// ---------------------------------------------------------------------------
extern "C" void kernel_launch(void* const* d_in, const int* in_sizes, int n_in,
                              void* d_out, int out_size)
{
    const float* x = (const float*)d_in[0];
    const float* w_ih[3] = {(const float*)d_in[1], (const float*)d_in[5], (const float*)d_in[9]};
    const float* w_hh[3] = {(const float*)d_in[2], (const float*)d_in[6], (const float*)d_in[10]};
    const float* b_ih[3] = {(const float*)d_in[3], (const float*)d_in[7], (const float*)d_in[11]};
    const float* b_hh[3] = {(const float*)d_in[4], (const float*)d_in[8], (const float*)d_in[12]};
    const float* pw = (const float*)d_in[13];
    const float* pb = (const float*)d_in[14];
    float* out = (float*)d_out;

    float *xg_p, *hs0_p, *hs1_p, *hb_p, *c_p;
    cudaGetSymbolAddress((void**)&xg_p, g_xg);
    cudaGetSymbolAddress((void**)&hs0_p, g_hseq0);
    cudaGetSymbolAddress((void**)&hs1_p, g_hseq1);
    cudaGetSymbolAddress((void**)&hb_p, g_hbuf);
    cudaGetSymbolAddress((void**)&c_p, g_c);
    float* hb0 = hb_p;
    float* hb1 = hb_p + BB * HH;

    const float* inA[3] = {x, hs0_p, hs1_p};
    float* outH[3] = {hs0_p, hs1_p, hs0_p};
    int Ks[3] = {NM, HH, HH};

    for (int l = 0; l < 3; l++) {
        zero2_kernel<<<(BB * HH + 255) / 256, 256>>>(hb0, c_p, BB * HH);
        dim3 g1((BB * TT) / 64, GG / 64);
        gemm_in_kernel<<<g1, 256>>>(inA[l], w_ih[l], b_ih[l], b_hh[l], xg_p, Ks[l]);
        for (int t = 0; t < TT; t++) {
            const float* hi = (t & 1) ? hb1 : hb0;
            float* ho = (t & 1) ? hb0 : hb1;
            lstm_step_kernel<<<dim3(8, 12), 256>>>(w_hh[l], xg_p, hi, ho, c_p, outH[l], t);
        }
    }
    proj_kernel<<<BB / 8, 256>>>(hb0, pw, pb, out);
}

// round 2
// speedup vs baseline: 1.7218x; 1.7218x over previous
#include <cuda_runtime.h>
#include <cstdint>
#include <math.h>

#define BB 512
#define TT 180
#define NM 40
#define HH 768
#define GG 3072   // 4*HH
#define PR 256
#define KC 48     // HH/16

// ---- static device scratch ----
__device__ float g_xg[(size_t)TT * BB * GG];      // [t][b][gcol]
__device__ float g_hseq0[(size_t)BB * TT * HH];
__device__ float g_hseq1[(size_t)BB * TT * HH];
__device__ float g_hfrag[2 * BB * HH];            // A-frag-ordered tf32 h (ping-pong)
__device__ float g_c[BB * HH];
__device__ float g_whhf[GG * HH];                 // B-frag-ordered tf32 W_hh
__device__ float g_wihf[GG * HH];                 // B-frag-ordered tf32 W_ih (Kc*16 cols)
__device__ float g_bias[GG];

__device__ __forceinline__ uint32_t f2tf(float f) {
    uint32_t u;
    asm("cvt.rna.tf32.f32 %0, %1;" : "=r"(u) : "f"(f));
    return u;
}

__device__ __forceinline__ void mma_(float* d, const uint32_t* a, uint32_t b0, uint32_t b1) {
    asm volatile(
        "mma.sync.aligned.m16n8k8.row.col.f32.tf32.tf32.f32 "
        "{%0,%1,%2,%3}, {%4,%5,%6,%7}, {%8,%9}, {%0,%1,%2,%3};\n"
        : "+f"(d[0]), "+f"(d[1]), "+f"(d[2]), "+f"(d[3])
        : "r"(a[0]), "r"(a[1]), "r"(a[2]), "r"(a[3]), "r"(b0), "r"(b1));
}

__device__ __forceinline__ void cp16(float* s, const float* g) {
    uint32_t sa = (uint32_t)__cvta_generic_to_shared(s);
    asm volatile("cp.async.cg.shared.global [%0], [%1], 16;\n" :: "r"(sa), "l"(g));
}
#define CPCOMMIT() asm volatile("cp.async.commit_group;\n")
#define CPWAIT0()  asm volatile("cp.async.wait_group 0;\n")

__device__ __forceinline__ float sigf(float x) { return 1.f / (1.f + expf(-x)); }

// ---------------------------------------------------------------------------
// Prepass: W_hh [GG][HH] -> B-frag order [j0 12][k16 48][ntile 32][lane 32][reg 4]
// ncol = gate*64 + cj  (warp wn == gate in step kernel)
// ---------------------------------------------------------------------------
__global__ void frag_whh_kernel(const float* __restrict__ W, float* __restrict__ out) {
    int idx = blockIdx.x * 256 + threadIdx.x;
    if (idx >= GG * HH) return;
    int r = idx / HH, k = idx - r * HH;
    int gate = r / HH;          // 0..3
    int jglob = r - gate * HH;
    int j0 = jglob >> 6, cj = jglob & 63;
    int ncol = gate * 64 + cj;
    int k16 = k >> 4, kl = k & 15, k8 = kl >> 3, k8i = kl & 7;
    int lane = (ncol & 7) * 4 + (k8i & 3);
    int reg = k8 * 2 + (k8i >> 2);
    size_t dst = ((((size_t)j0 * KC + k16) * 32 + (ncol >> 3)) * 32 + lane) * 4 + reg;
    out[dst] = __uint_as_float(f2tf(W[idx]));
}

// ---------------------------------------------------------------------------
// Prepass: W_ih [GG][K] -> B-frag order [n0 24][k16 Kc][ntile 16][lane 32][reg 4]
// (pads k >= K with zeros)
// ---------------------------------------------------------------------------
__global__ void frag_wih_kernel(const float* __restrict__ W, float* __restrict__ out,
                                int K, int Kc) {
    int kb = Kc * 16;
    int idx = blockIdx.x * 256 + threadIdx.x;
    if (idx >= GG * kb) return;
    int r = idx / kb, k = idx - r * kb;
    int n0 = r >> 7, ncol = r & 127;
    int k16 = k >> 4, kl = k & 15, k8 = kl >> 3, k8i = kl & 7;
    int lane = (ncol & 7) * 4 + (k8i & 3);
    int reg = k8 * 2 + (k8i >> 2);
    size_t dst = ((((size_t)n0 * Kc + k16) * 16 + (ncol >> 3)) * 32 + lane) * 4 + reg;
    float v = (k < K) ? W[(size_t)r * K + k] : 0.f;
    out[dst] = __uint_as_float(f2tf(v));
}

// ---------------------------------------------------------------------------
// Per-layer prep: combined bias, zero h-frag (t=0 input) and cell state
// ---------------------------------------------------------------------------
__global__ void prep_kernel(const float* __restrict__ bi, const float* __restrict__ bh,
                            float* __restrict__ bias, float* __restrict__ hf,
                            float* __restrict__ c) {
    int i = blockIdx.x * 256 + threadIdx.x;
    if (i < GG) bias[i] = bi[i] + bh[i];
    if (i < BB * HH) { hf[i] = 0.f; c[i] = 0.f; }
}

// ---------------------------------------------------------------------------
// Input GEMM: out[t][b][col] = bias[col] + A[m][:] . W[col][:],  m = b*TT + t
// CTA 128m x 128n, 8 warps (4m x 2n), warp 32m x 64n. cp.async B (pre-fragged),
// LDG+cvt+STS A (frag order). Double buffered.
// ---------------------------------------------------------------------------
__global__ __launch_bounds__(256) void gemm_in2(
    const float* __restrict__ A, const float* __restrict__ Bf,
    const float* __restrict__ bias, float* __restrict__ out, int K, int Kc)
{
    __shared__ __align__(16) float As[2][2048];   // [mtile 8][k8 2][lane 32][reg 4]
    __shared__ __align__(16) float Bs[2][2048];   // [ntile 16][lane 32][reg 4]
    const int tid = threadIdx.x, lane = tid & 31, wid = tid >> 5;
    const int wm = wid >> 1, wn = wid & 1;
    const int m0 = blockIdx.x, n0 = blockIdx.y;
    const int g = lane >> 2, tg = lane & 3;

    float acc[2][8][4];
    #pragma unroll
    for (int i = 0; i < 2; i++)
        #pragma unroll
        for (int j = 0; j < 8; j++)
            #pragma unroll
            for (int k = 0; k < 4; k++) acc[i][j][k] = 0.f;

    const int row = tid >> 1, kp = (tid & 1) * 8;
    const float* Arow = A + (size_t)(m0 * 128 + row) * K;
    const float* Bbase = Bf + (size_t)n0 * Kc * 2048;

    float a0[4], a1[4];
    auto ldgA = [&](int kc) {
        int k0 = kc * 16;
        #pragma unroll
        for (int e = 0; e < 4; e++) { a0[e] = 0.f; a1[e] = 0.f; }
        if (k0 + kp < K)     *(float4*)a0 = *(const float4*)(Arow + k0 + kp);
        if (k0 + kp + 4 < K) *(float4*)a1 = *(const float4*)(Arow + k0 + kp + 4);
    };
    auto stsA = [&](int buf) {
        int mtile = row >> 4;
        int mhi = ((row & 15) >= 8) ? 1 : 0;
        #pragma unroll
        for (int e = 0; e < 8; e++) {
            int kl = kp + ((e >= 4) ? 4 : 0) + (e & 3);
            float v = (e < 4) ? a0[e & 3] : a1[e & 3];
            int k8 = kl >> 3, k8i = kl & 7;
            int lf = (row & 7) * 4 + (k8i & 3);
            int reg = (k8i >> 2) * 2 + mhi;
            As[buf][((mtile * 2 + k8) * 32 + lf) * 4 + reg] = __uint_as_float(f2tf(v));
        }
    };
    auto cpB = [&](int buf, int kc) {
        const float* src = Bbase + (size_t)kc * 2048;
        cp16(&Bs[buf][tid * 4], src + tid * 4);
        cp16(&Bs[buf][(tid + 256) * 4], src + (tid + 256) * 4);
    };

    ldgA(0); cpB(0, 0); CPCOMMIT();
    stsA(0);
    CPWAIT0();
    __syncthreads();

    for (int kc = 0; kc < Kc; kc++) {
        int cur = kc & 1, nxt = cur ^ 1;
        if (kc + 1 < Kc) { cpB(nxt, kc + 1); CPCOMMIT(); ldgA(kc + 1); }
        uint32_t af[2][2][4];
        #pragma unroll
        for (int mt = 0; mt < 2; mt++)
            #pragma unroll
            for (int k8 = 0; k8 < 2; k8++)
                *(uint4*)af[mt][k8] =
                    *(const uint4*)&As[cur][(((2 * wm + mt) * 2 + k8) * 32 + lane) * 4];
        #pragma unroll
        for (int nt = 0; nt < 8; nt++) {
            uint4 b = *(const uint4*)&Bs[cur][((wn * 8 + nt) * 32 + lane) * 4];
            mma_(acc[0][nt], af[0][0], b.x, b.y);
            mma_(acc[1][nt], af[1][0], b.x, b.y);
            mma_(acc[0][nt], af[0][1], b.z, b.w);
            mma_(acc[1][nt], af[1][1], b.z, b.w);
        }
        if (kc + 1 < Kc) { stsA(nxt); CPWAIT0(); }
        __syncthreads();
    }

    #pragma unroll
    for (int mt = 0; mt < 2; mt++)
        #pragma unroll
        for (int nt = 0; nt < 8; nt++)
            #pragma unroll
            for (int r2 = 0; r2 < 4; r2++) {
                int rrow = wm * 32 + mt * 16 + g + ((r2 & 2) ? 8 : 0);
                int m = m0 * 128 + rrow;
                int col = n0 * 128 + wn * 64 + nt * 8 + 2 * tg + (r2 & 1);
                int b = m / TT, t = m - b * TT;
                out[((size_t)t * BB + b) * GG + col] = acc[mt][nt][r2] + __ldg(&bias[col]);
            }
}

// ---------------------------------------------------------------------------
// LSTM step: gates = xg[t] + h @ W_hh^T, pointwise update. All operands
// pre-fragged in gmem -> pure cp.async + LDS.128 mainloop.
// CTA 64 batch x 64 hidden (256 gate cols). 8 warps: wm(2) x wn(4); wn == gate.
// ---------------------------------------------------------------------------
__global__ __launch_bounds__(256) void lstm_step2(
    const float* __restrict__ Wf, const float* __restrict__ xg,
    const float* __restrict__ hin, float* __restrict__ hout,
    float* __restrict__ cst, float* __restrict__ hseq, int t)
{
    __shared__ __align__(16) float sm[10240];  // As[2][1024] @0, Bs[2][4096] @2048; epilogue overlay
    const int tid = threadIdx.x, lane = tid & 31, wid = tid >> 5;
    const int wm = wid >> 2, wn = wid & 3;
    const int m0 = blockIdx.x, j0 = blockIdx.y;
    const int g = lane >> 2, tg = lane & 3;
    const float* Ab = hin + (size_t)m0 * (KC * 1024);
    const float* Bb = Wf + (size_t)j0 * (KC * 4096);

    float acc[2][8][4];
    #pragma unroll
    for (int i = 0; i < 2; i++)
        #pragma unroll
        for (int j = 0; j < 8; j++)
            #pragma unroll
            for (int k = 0; k < 4; k++) acc[i][j][k] = 0.f;

    auto cpAB = [&](int buf, int kc) {
        const float* a = Ab + (size_t)kc * 1024;
        const float* b = Bb + (size_t)kc * 4096;
        cp16(&sm[buf * 1024 + tid * 4], a + tid * 4);
        #pragma unroll
        for (int i = 0; i < 4; i++)
            cp16(&sm[2048 + buf * 4096 + (tid + i * 256) * 4], b + (tid + i * 256) * 4);
    };

    cpAB(0, 0); CPCOMMIT();
    CPWAIT0();
    __syncthreads();

    for (int kc = 0; kc < KC; kc++) {
        int cur = kc & 1, nxt = cur ^ 1;
        if (kc + 1 < KC) { cpAB(nxt, kc + 1); CPCOMMIT(); }
        uint32_t af[2][2][4];
        #pragma unroll
        for (int mt = 0; mt < 2; mt++)
            #pragma unroll
            for (int k8 = 0; k8 < 2; k8++)
                *(uint4*)af[mt][k8] =
                    *(const uint4*)&sm[cur * 1024 + (((2 * wm + mt) * 2 + k8) * 32 + lane) * 4];
        #pragma unroll
        for (int nt = 0; nt < 8; nt++) {
            uint4 b = *(const uint4*)&sm[2048 + cur * 4096 + ((wn * 8 + nt) * 32 + lane) * 4];
            mma_(acc[0][nt], af[0][0], b.x, b.y);
            mma_(acc[1][nt], af[1][0], b.x, b.y);
            mma_(acc[0][nt], af[0][1], b.z, b.w);
            mma_(acc[1][nt], af[1][1], b.z, b.w);
        }
        if (kc + 1 < KC) CPWAIT0();
        __syncthreads();
    }

    // epilogue: gather 4 gates per (b,j) via smem, two 32-row passes
    float* gsm = sm;  // [m32][gate][cj], stride mi*260 + gate*65 + cj  (8318 < 10240)
    for (int p = 0; p < 2; p++) {
        __syncthreads();
        if (wm == p) {
            #pragma unroll
            for (int mt = 0; mt < 2; mt++)
                #pragma unroll
                for (int nt = 0; nt < 8; nt++)
                    #pragma unroll
                    for (int r2 = 0; r2 < 4; r2++) {
                        int mi = mt * 16 + g + ((r2 & 2) ? 8 : 0);
                        int cj = nt * 8 + 2 * tg + (r2 & 1);
                        gsm[mi * 260 + wn * 65 + cj] = acc[mt][nt][r2];
                    }
        }
        __syncthreads();
        int cj = tid & 63, r0 = tid >> 6;
        #pragma unroll
        for (int r = r0; r < 32; r += 4) {
            int b = m0 * 64 + p * 32 + r;
            int j = j0 * 64 + cj;
            size_t xb = ((size_t)t * BB + b) * GG + j;
            float pi = gsm[r * 260 + 0 * 65 + cj] + xg[xb];
            float pf = gsm[r * 260 + 1 * 65 + cj] + xg[xb + HH];
            float pg = gsm[r * 260 + 2 * 65 + cj] + xg[xb + 2 * HH];
            float po = gsm[r * 260 + 3 * 65 + cj] + xg[xb + 3 * HH];
            float iv = sigf(pi), fv = sigf(pf), gv = tanhf(pg), ov = sigf(po);
            size_t ci = (size_t)b * HH + j;
            float cn = fv * cst[ci] + iv * gv;
            cst[ci] = cn;
            float hn = ov * tanhf(cn);
            hseq[((size_t)b * TT + t) * HH + j] = hn;
            // scatter h into A-frag layout (tf32 bits)
            int k16 = j >> 4, k8 = (j >> 3) & 1;
            int lf = (b & 7) * 4 + (j & 3);
            int reg = ((j >> 2) & 1) * 2 + (((b & 15) >= 8) ? 1 : 0);
            int mtile = (b >> 4) & 3;
            hout[((((((size_t)m0 * KC + k16) * 4 + mtile) * 2 + k8) * 32 + lf) * 4) + reg] =
                __uint_as_float(f2tf(hn));
        }
    }
}

// ---------------------------------------------------------------------------
// Projection + L2 normalize from hseq[:, T-1, :]
// ---------------------------------------------------------------------------
__global__ __launch_bounds__(256) void proj_kernel(
    const float* __restrict__ hseq, const float* __restrict__ pw,
    const float* __restrict__ pb, float* __restrict__ out)
{
    __shared__ float hs[8][HH];
    __shared__ float red[256];
    const int b0 = blockIdx.x * 8;
    const int tid = threadIdx.x;

    for (int i = tid; i < 8 * HH; i += 256) {
        int r = i / HH, k = i % HH;
        hs[r][k] = hseq[((size_t)(b0 + r) * TT + (TT - 1)) * HH + k];
    }
    __syncthreads();

    float s[8];
    float bias = pb[tid];
    #pragma unroll
    for (int r = 0; r < 8; r++) s[r] = bias;
    const float* w = pw + (size_t)tid * HH;
    for (int k = 0; k < HH; k++) {
        float wv = w[k];
        #pragma unroll
        for (int r = 0; r < 8; r++) s[r] += wv * hs[r][k];
    }

    for (int r = 0; r < 8; r++) {
        red[tid] = s[r] * s[r];
        __syncthreads();
        for (int off = 128; off > 0; off >>= 1) {
            if (tid < off) red[tid] += red[tid + off];
            __syncthreads();
        }
        float rn = rsqrtf(red[0]);
        __syncthreads();
        out[(size_t)(b0 + r) * PR + tid] = s[r] * rn;
    }
}

// ---------------------------------------------------------------------------
// host
// ---------------------------------------------------------------------------
extern "C" void kernel_launch(void* const* d_in, const int* in_sizes, int n_in,
                              void* d_out, int out_size)
{
    const float* x = (const float*)d_in[0];
    const float* w_ih[3] = {(const float*)d_in[1], (const float*)d_in[5], (const float*)d_in[9]};
    const float* w_hh[3] = {(const float*)d_in[2], (const float*)d_in[6], (const float*)d_in[10]};
    const float* b_ih[3] = {(const float*)d_in[3], (const float*)d_in[7], (const float*)d_in[11]};
    const float* b_hh[3] = {(const float*)d_in[4], (const float*)d_in[8], (const float*)d_in[12]};
    const float* pw = (const float*)d_in[13];
    const float* pb = (const float*)d_in[14];
    float* out = (float*)d_out;

    float *xg_p, *hs0_p, *hs1_p, *hf_p, *c_p, *whhf_p, *wihf_p, *bias_p;
    cudaGetSymbolAddress((void**)&xg_p, g_xg);
    cudaGetSymbolAddress((void**)&hs0_p, g_hseq0);
    cudaGetSymbolAddress((void**)&hs1_p, g_hseq1);
    cudaGetSymbolAddress((void**)&hf_p, g_hfrag);
    cudaGetSymbolAddress((void**)&c_p, g_c);
    cudaGetSymbolAddress((void**)&whhf_p, g_whhf);
    cudaGetSymbolAddress((void**)&wihf_p, g_wihf);
    cudaGetSymbolAddress((void**)&bias_p, g_bias);
    float* hf0 = hf_p;
    float* hf1 = hf_p + BB * HH;

    const float* inA[3] = {x, hs0_p, hs1_p};
    float* outH[3] = {hs0_p, hs1_p, hs0_p};
    int Ks[3] = {NM, HH, HH};
    int Kcs[3] = {3, KC, KC};

    for (int l = 0; l < 3; l++) {
        int nW = GG * Kcs[l] * 16;
        frag_wih_kernel<<<(nW + 255) / 256, 256>>>(w_ih[l], wihf_p, Ks[l], Kcs[l]);
        frag_whh_kernel<<<(GG * HH + 255) / 256, 256>>>(w_hh[l], whhf_p);
        prep_kernel<<<(BB * HH + 255) / 256, 256>>>(b_ih[l], b_hh[l], bias_p, hf0, c_p);
        gemm_in2<<<dim3((BB * TT) / 128, GG / 128), 256>>>(inA[l], wihf_p, bias_p, xg_p,
                                                           Ks[l], Kcs[l]);
        for (int t = 0; t < TT; t++) {
            const float* hi = (t & 1) ? hf1 : hf0;
            float* ho = (t & 1) ? hf0 : hf1;
            lstm_step2<<<dim3(8, 12), 256>>>(whhf_p, xg_p, hi, ho, c_p, outH[l], t);
        }
    }
    proj_kernel<<<BB / 8, 256>>>(hs0_p, pw, pb, out);
}

// round 3
// speedup vs baseline: 1.9240x; 1.1175x over previous
#include <cuda_runtime.h>
#include <cstdint>
#include <math.h>

#define BB 512
#define TT 180
#define NM 40
#define HH 768
#define GG 3072   // 4*HH
#define PR 256
#define KC 48     // HH/16
#define NCTA 96

// ---- static device scratch ----
__device__ float g_xg[(size_t)TT * BB * GG];      // [t][b][gcol]
__device__ float g_hseq0[(size_t)BB * TT * HH];
__device__ float g_hseq1[(size_t)BB * TT * HH];
__device__ float g_hfrag[2 * BB * HH];            // A-frag-ordered tf32 h (ping-pong)
__device__ float g_c[BB * HH];
__device__ float g_whhf[GG * HH];                 // B-frag-ordered tf32 W_hh
__device__ float g_wihf[GG * HH];                 // B-frag-ordered tf32 W_ih
__device__ float g_bias[GG];
__device__ unsigned g_bar;

__device__ __forceinline__ uint32_t f2tf(float f) {
    uint32_t u;
    asm("cvt.rna.tf32.f32 %0, %1;" : "=r"(u) : "f"(f));
    return u;
}

__device__ __forceinline__ void mma_(float* d, const uint32_t* a, uint32_t b0, uint32_t b1) {
    asm volatile(
        "mma.sync.aligned.m16n8k8.row.col.f32.tf32.tf32.f32 "
        "{%0,%1,%2,%3}, {%4,%5,%6,%7}, {%8,%9}, {%0,%1,%2,%3};\n"
        : "+f"(d[0]), "+f"(d[1]), "+f"(d[2]), "+f"(d[3])
        : "r"(a[0]), "r"(a[1]), "r"(a[2]), "r"(a[3]), "r"(b0), "r"(b1));
}

__device__ __forceinline__ void cp16(float* s, const float* g) {
    uint32_t sa = (uint32_t)__cvta_generic_to_shared(s);
    asm volatile("cp.async.cg.shared.global [%0], [%1], 16;\n" :: "r"(sa), "l"(g));
}
#define CPCOMMIT() asm volatile("cp.async.commit_group;\n")
#define CPW0() asm volatile("cp.async.wait_group 0;\n")
#define CPW1() asm volatile("cp.async.wait_group 1;\n")
#define CPW2() asm volatile("cp.async.wait_group 2;\n")

__device__ __forceinline__ float sigf(float x) { return 1.f / (1.f + expf(-x)); }

// ---------------------------------------------------------------------------
// Prepass: W_hh [GG][HH] -> B-frag order [j0 12][k16 48][ntile 32][lane 32][reg 4]
// ---------------------------------------------------------------------------
__global__ void frag_whh_kernel(const float* __restrict__ W, float* __restrict__ out) {
    int idx = blockIdx.x * 256 + threadIdx.x;
    if (idx >= GG * HH) return;
    int r = idx / HH, k = idx - r * HH;
    int gate = r / HH;
    int jglob = r - gate * HH;
    int j0 = jglob >> 6, cj = jglob & 63;
    int ncol = gate * 64 + cj;
    int k16 = k >> 4, kl = k & 15, k8 = kl >> 3, k8i = kl & 7;
    int lane = (ncol & 7) * 4 + (k8i & 3);
    int reg = k8 * 2 + (k8i >> 2);
    size_t dst = ((((size_t)j0 * KC + k16) * 32 + (ncol >> 3)) * 32 + lane) * 4 + reg;
    out[dst] = __uint_as_float(f2tf(W[idx]));
}

// ---------------------------------------------------------------------------
// Prepass: W_ih [GG][K] -> B-frag order [n0 24][k16 Kc][ntile 16][lane 32][reg 4]
// ---------------------------------------------------------------------------
__global__ void frag_wih_kernel(const float* __restrict__ W, float* __restrict__ out,
                                int K, int Kc) {
    int kb = Kc * 16;
    int idx = blockIdx.x * 256 + threadIdx.x;
    if (idx >= GG * kb) return;
    int r = idx / kb, k = idx - r * kb;
    int n0 = r >> 7, ncol = r & 127;
    int k16 = k >> 4, kl = k & 15, k8 = kl >> 3, k8i = kl & 7;
    int lane = (ncol & 7) * 4 + (k8i & 3);
    int reg = k8 * 2 + (k8i >> 2);
    size_t dst = ((((size_t)n0 * Kc + k16) * 16 + (ncol >> 3)) * 32 + lane) * 4 + reg;
    float v = (k < K) ? W[(size_t)r * K + k] : 0.f;
    out[dst] = __uint_as_float(f2tf(v));
}

// ---------------------------------------------------------------------------
// Per-layer prep: bias, zero h-frag + c + barrier counter
// ---------------------------------------------------------------------------
__global__ void prep_kernel(const float* __restrict__ bi, const float* __restrict__ bh,
                            float* __restrict__ bias, float* __restrict__ hf,
                            float* __restrict__ c) {
    int i = blockIdx.x * 256 + threadIdx.x;
    if (i == 0) g_bar = 0u;
    if (i < GG) bias[i] = bi[i] + bh[i];
    if (i < BB * HH) { hf[i] = 0.f; c[i] = 0.f; }
}

// ---------------------------------------------------------------------------
// Input GEMM. Grid: (GG/128, (BB*TT)/128) so n-tiles vary fastest (A reuse in wave)
// ---------------------------------------------------------------------------
__global__ __launch_bounds__(256) void gemm_in2(
    const float* __restrict__ A, const float* __restrict__ Bf,
    const float* __restrict__ bias, float* __restrict__ out, int K, int Kc)
{
    __shared__ __align__(16) float As[2][2048];
    __shared__ __align__(16) float Bs[2][2048];
    const int tid = threadIdx.x, lane = tid & 31, wid = tid >> 5;
    const int wm = wid >> 1, wn = wid & 1;
    const int n0 = blockIdx.x, m0 = blockIdx.y;
    const int g = lane >> 2, tg = lane & 3;

    float acc[2][8][4];
    #pragma unroll
    for (int i = 0; i < 2; i++)
        #pragma unroll
        for (int j = 0; j < 8; j++)
            #pragma unroll
            for (int k = 0; k < 4; k++) acc[i][j][k] = 0.f;

    const int row = tid >> 1, kp = (tid & 1) * 8;
    const float* Arow = A + (size_t)(m0 * 128 + row) * K;
    const float* Bbase = Bf + (size_t)n0 * Kc * 2048;

    float a0[4], a1[4];
    auto ldgA = [&](int kc) {
        int k0 = kc * 16;
        #pragma unroll
        for (int e = 0; e < 4; e++) { a0[e] = 0.f; a1[e] = 0.f; }
        if (k0 + kp < K)     *(float4*)a0 = *(const float4*)(Arow + k0 + kp);
        if (k0 + kp + 4 < K) *(float4*)a1 = *(const float4*)(Arow + k0 + kp + 4);
    };
    auto stsA = [&](int buf) {
        int mtile = row >> 4;
        int mhi = ((row & 15) >= 8) ? 1 : 0;
        #pragma unroll
        for (int e = 0; e < 8; e++) {
            int kl = kp + ((e >= 4) ? 4 : 0) + (e & 3);
            float v = (e < 4) ? a0[e & 3] : a1[e & 3];
            int k8 = kl >> 3, k8i = kl & 7;
            int lf = (row & 7) * 4 + (k8i & 3);
            int reg = (k8i >> 2) * 2 + mhi;
            As[buf][((mtile * 2 + k8) * 32 + lf) * 4 + reg] = __uint_as_float(f2tf(v));
        }
    };
    auto cpB = [&](int buf, int kc) {
        const float* src = Bbase + (size_t)kc * 2048;
        cp16(&Bs[buf][tid * 4], src + tid * 4);
        cp16(&Bs[buf][(tid + 256) * 4], src + (tid + 256) * 4);
    };

    ldgA(0); cpB(0, 0); CPCOMMIT();
    stsA(0);
    CPW0();
    __syncthreads();

    for (int kc = 0; kc < Kc; kc++) {
        int cur = kc & 1, nxt = cur ^ 1;
        if (kc + 1 < Kc) { cpB(nxt, kc + 1); CPCOMMIT(); ldgA(kc + 1); }
        uint32_t af[2][2][4];
        #pragma unroll
        for (int mt = 0; mt < 2; mt++)
            #pragma unroll
            for (int k8 = 0; k8 < 2; k8++)
                *(uint4*)af[mt][k8] =
                    *(const uint4*)&As[cur][(((2 * wm + mt) * 2 + k8) * 32 + lane) * 4];
        #pragma unroll
        for (int nt = 0; nt < 8; nt++) {
            uint4 b = *(const uint4*)&Bs[cur][((wn * 8 + nt) * 32 + lane) * 4];
            mma_(acc[0][nt], af[0][0], b.x, b.y);
            mma_(acc[1][nt], af[1][0], b.x, b.y);
            mma_(acc[0][nt], af[0][1], b.z, b.w);
            mma_(acc[1][nt], af[1][1], b.z, b.w);
        }
        if (kc + 1 < Kc) { stsA(nxt); CPW0(); }
        __syncthreads();
    }

    #pragma unroll
    for (int mt = 0; mt < 2; mt++)
        #pragma unroll
        for (int nt = 0; nt < 8; nt++)
            #pragma unroll
            for (int r2 = 0; r2 < 4; r2++) {
                int rrow = wm * 32 + mt * 16 + g + ((r2 & 2) ? 8 : 0);
                int m = m0 * 128 + rrow;
                int col = n0 * 128 + wn * 64 + nt * 8 + 2 * tg + (r2 & 1);
                int b = m / TT, t = m - b * TT;
                out[((size_t)t * BB + b) * GG + col] = acc[mt][nt][r2] + __ldg(&bias[col]);
            }
}

// ---------------------------------------------------------------------------
// Persistent LSTM layer: one launch runs all TT timesteps.
// 96 CTAs (8 batch-tiles x 12 j-tiles), 4-stage cp.async pipeline,
// grid-wide barrier between steps.
// Dynamic smem: stages 4*5120 floats | gsm 8320 | fs 4096  = 32896 floats.
// ---------------------------------------------------------------------------
__global__ __launch_bounds__(256, 1) void lstm_persist(
    const float* __restrict__ Wf, const float* __restrict__ xg,
    float* __restrict__ hfA, float* __restrict__ hfB,
    float* __restrict__ cst, float* __restrict__ hseq, int seq_all)
{
    extern __shared__ __align__(16) float sm[];
    const int tid = threadIdx.x, lane = tid & 31, wid = tid >> 5;
    const int wm = wid >> 2, wn = wid & 3;
    const int m0 = blockIdx.x & 7, j0 = blockIdx.x >> 3;
    const int g = lane >> 2, tg = lane & 3;
    const float* Bb = Wf + (size_t)j0 * (KC * 4096);
    float* gsm = sm + 20480;
    float* fs  = sm + 28800;

    for (int t = 0; t < TT; t++) {
        const float* Ain = ((t & 1) ? hfB : hfA) + (size_t)m0 * (KC * 1024);
        float* Hout = (t & 1) ? hfA : hfB;

        auto cpAB = [&](int kc) {
            float* dst = sm + (kc & 3) * 5120;
            const float* a = Ain + (size_t)kc * 1024;
            const float* b = Bb + (size_t)kc * 4096;
            cp16(&dst[tid * 4], a + tid * 4);
            #pragma unroll
            for (int i = 0; i < 4; i++)
                cp16(&dst[1024 + (tid + i * 256) * 4], b + (tid + i * 256) * 4);
        };

        float acc[2][8][4];
        #pragma unroll
        for (int i = 0; i < 2; i++)
            #pragma unroll
            for (int j = 0; j < 8; j++)
                #pragma unroll
                for (int k = 0; k < 4; k++) acc[i][j][k] = 0.f;

        cpAB(0); CPCOMMIT();
        cpAB(1); CPCOMMIT();
        cpAB(2); CPCOMMIT();

        for (int kc = 0; kc < KC; kc++) {
            if (kc < KC - 2) CPW2(); else if (kc == KC - 2) CPW1(); else CPW0();
            __syncthreads();
            if (kc + 3 < KC) { cpAB(kc + 3); CPCOMMIT(); }
            const float* stg = sm + (kc & 3) * 5120;
            uint32_t af[2][2][4];
            #pragma unroll
            for (int mt = 0; mt < 2; mt++)
                #pragma unroll
                for (int k8 = 0; k8 < 2; k8++)
                    *(uint4*)af[mt][k8] =
                        *(const uint4*)&stg[(((2 * wm + mt) * 2 + k8) * 32 + lane) * 4];
            #pragma unroll
            for (int nt = 0; nt < 8; nt++) {
                uint4 b = *(const uint4*)&stg[1024 + ((wn * 8 + nt) * 32 + lane) * 4];
                mma_(acc[0][nt], af[0][0], b.x, b.y);
                mma_(acc[1][nt], af[1][0], b.x, b.y);
                mma_(acc[0][nt], af[0][1], b.z, b.w);
                mma_(acc[1][nt], af[1][1], b.z, b.w);
            }
        }

        // ---- epilogue: two 32-row passes through smem gate transpose ----
        for (int p = 0; p < 2; p++) {
            __syncthreads();
            if (wm == p) {
                #pragma unroll
                for (int mt = 0; mt < 2; mt++)
                    #pragma unroll
                    for (int nt = 0; nt < 8; nt++)
                        #pragma unroll
                        for (int r2 = 0; r2 < 4; r2++) {
                            int mi = mt * 16 + g + ((r2 & 2) ? 8 : 0);
                            int cj = nt * 8 + 2 * tg + (r2 & 1);
                            gsm[mi * 260 + wn * 65 + cj] = acc[mt][nt][r2];
                        }
            }
            __syncthreads();
            int cj = tid & 63, r0 = tid >> 6;
            #pragma unroll
            for (int r = r0; r < 32; r += 4) {
                int bl = p * 32 + r;
                int b = m0 * 64 + bl;
                int j = j0 * 64 + cj;
                size_t xb = ((size_t)t * BB + b) * GG + j;
                float pi = gsm[r * 260 + 0 * 65 + cj] + xg[xb];
                float pf = gsm[r * 260 + 1 * 65 + cj] + xg[xb + HH];
                float pg = gsm[r * 260 + 2 * 65 + cj] + xg[xb + 2 * HH];
                float po = gsm[r * 260 + 3 * 65 + cj] + xg[xb + 3 * HH];
                float iv = sigf(pi), fv = sigf(pf), gv = tanhf(pg), ov = sigf(po);
                size_t ci = (size_t)b * HH + j;
                float cn = fv * cst[ci] + iv * gv;
                cst[ci] = cn;
                float hn = ov * tanhf(cn);
                if (seq_all || t == TT - 1)
                    hseq[((size_t)b * TT + t) * HH + j] = hn;
                int q = cj >> 4, k8 = (cj >> 3) & 1;
                int lf = (bl & 7) * 4 + (cj & 3);
                int reg = ((cj >> 2) & 1) * 2 + (((bl & 15) >= 8) ? 1 : 0);
                int mtile = bl >> 4;
                fs[((q * 4 + mtile) * 2 + k8) * 128 + lf * 4 + reg] =
                    __uint_as_float(f2tf(hn));
            }
        }
        __syncthreads();
        if (t < TT - 1) {
            // coalesced frag store for next step's A operand
            size_t fb = ((size_t)m0 * KC + (size_t)j0 * 4) * 1024;
            for (int i = tid; i < 1024; i += 256)
                *(float4*)&Hout[fb + i * 4] = *(const float4*)&fs[i * 4];
            // grid-wide barrier
            __threadfence();
            __syncthreads();
            if (tid == 0) {
                atomicAdd(&g_bar, 1u);
                unsigned target = (unsigned)NCTA * (unsigned)(t + 1);
                while (atomicAdd(&g_bar, 0u) < target) { }
            }
            __syncthreads();
            __threadfence();
        }
    }
}

// ---------------------------------------------------------------------------
// Projection + L2 normalize from hseq[:, T-1, :]
// ---------------------------------------------------------------------------
__global__ __launch_bounds__(256) void proj_kernel(
    const float* __restrict__ hseq, const float* __restrict__ pw,
    const float* __restrict__ pb, float* __restrict__ out)
{
    __shared__ float hs[8][HH];
    __shared__ float red[256];
    const int b0 = blockIdx.x * 8;
    const int tid = threadIdx.x;

    for (int i = tid; i < 8 * HH; i += 256) {
        int r = i / HH, k = i % HH;
        hs[r][k] = hseq[((size_t)(b0 + r) * TT + (TT - 1)) * HH + k];
    }
    __syncthreads();

    float s[8];
    float bias = pb[tid];
    #pragma unroll
    for (int r = 0; r < 8; r++) s[r] = bias;
    const float* w = pw + (size_t)tid * HH;
    for (int k = 0; k < HH; k++) {
        float wv = w[k];
        #pragma unroll
        for (int r = 0; r < 8; r++) s[r] += wv * hs[r][k];
    }

    for (int r = 0; r < 8; r++) {
        red[tid] = s[r] * s[r];
        __syncthreads();
        for (int off = 128; off > 0; off >>= 1) {
            if (tid < off) red[tid] += red[tid + off];
            __syncthreads();
        }
        float rn = rsqrtf(red[0]);
        __syncthreads();
        out[(size_t)(b0 + r) * PR + tid] = s[r] * rn;
    }
}

// ---------------------------------------------------------------------------
// host
// ---------------------------------------------------------------------------
extern "C" void kernel_launch(void* const* d_in, const int* in_sizes, int n_in,
                              void* d_out, int out_size)
{
    const float* x = (const float*)d_in[0];
    const float* w_ih[3] = {(const float*)d_in[1], (const float*)d_in[5], (const float*)d_in[9]};
    const float* w_hh[3] = {(const float*)d_in[2], (const float*)d_in[6], (const float*)d_in[10]};
    const float* b_ih[3] = {(const float*)d_in[3], (const float*)d_in[7], (const float*)d_in[11]};
    const float* b_hh[3] = {(const float*)d_in[4], (const float*)d_in[8], (const float*)d_in[12]};
    const float* pw = (const float*)d_in[13];
    const float* pb = (const float*)d_in[14];
    float* out = (float*)d_out;

    cudaFuncSetAttribute(lstm_persist, cudaFuncAttributeMaxDynamicSharedMemorySize, 131584);

    float *xg_p, *hs0_p, *hs1_p, *hf_p, *c_p, *whhf_p, *wihf_p, *bias_p;
    cudaGetSymbolAddress((void**)&xg_p, g_xg);
    cudaGetSymbolAddress((void**)&hs0_p, g_hseq0);
    cudaGetSymbolAddress((void**)&hs1_p, g_hseq1);
    cudaGetSymbolAddress((void**)&hf_p, g_hfrag);
    cudaGetSymbolAddress((void**)&c_p, g_c);
    cudaGetSymbolAddress((void**)&whhf_p, g_whhf);
    cudaGetSymbolAddress((void**)&wihf_p, g_wihf);
    cudaGetSymbolAddress((void**)&bias_p, g_bias);
    float* hf0 = hf_p;
    float* hf1 = hf_p + BB * HH;

    const float* inA[3] = {x, hs0_p, hs1_p};
    float* outH[3] = {hs0_p, hs1_p, hs0_p};
    int Ks[3] = {NM, HH, HH};
    int Kcs[3] = {3, KC, KC};

    for (int l = 0; l < 3; l++) {
        int nW = GG * Kcs[l] * 16;
        frag_wih_kernel<<<(nW + 255) / 256, 256>>>(w_ih[l], wihf_p, Ks[l], Kcs[l]);
        frag_whh_kernel<<<(GG * HH + 255) / 256, 256>>>(w_hh[l], whhf_p);
        prep_kernel<<<(BB * HH + 255) / 256, 256>>>(b_ih[l], b_hh[l], bias_p, hf0, c_p);
        gemm_in2<<<dim3(GG / 128, (BB * TT) / 128), 256>>>(inA[l], wihf_p, bias_p, xg_p,
                                                           Ks[l], Kcs[l]);
        lstm_persist<<<NCTA, 256, 131584>>>(whhf_p, xg_p, hf0, hf1, c_p, outH[l],
                                            (l < 2) ? 1 : 0);
    }
    proj_kernel<<<BB / 8, 256>>>(hs0_p, pw, pb, out);
}

// round 8
// speedup vs baseline: 3.5581x; 1.8493x over previous
#include <cuda_runtime.h>
#include <cuda_fp16.h>
#include <cstdint>
#include <math.h>

#define BB 512
#define TT 180
#define NM 40
#define HH 768
#define GG 3072   // 4*HH
#define PR 256
#define KC 48     // HH/16
#define NCTA 96

// ---- static device scratch ----
__device__ __half g_xg[(size_t)TT * BB * GG];        // [t][b][gcol] fp16
__device__ __half g_hseq0[(size_t)BB * TT * HH];
__device__ __half g_hseq1[(size_t)BB * TT * HH];
__device__ uint32_t g_hfrag[2 * 196608];             // A-frag fp16 h (ping-pong): [m0 8][kc 48][mt 4][lane 32][reg 4]
__device__ float g_c[BB * HH];
__device__ uint32_t g_whhf[1179648];                 // B-frag fp16 W_hh: [j0 12][kc 48][ntpair 16][lane 32][4]
__device__ uint32_t g_wihf[1179648];                 // B-frag fp16 W_ih: [n0 24][kc Kc][ntpair 8][lane 32][4]
__device__ float g_bias[GG];
__device__ unsigned g_bar;

__device__ __forceinline__ void mma16(float* d, uint4 a, uint32_t b0, uint32_t b1) {
    asm volatile(
        "mma.sync.aligned.m16n8k16.row.col.f32.f16.f16.f32 "
        "{%0,%1,%2,%3}, {%4,%5,%6,%7}, {%8,%9}, {%0,%1,%2,%3};\n"
        : "+f"(d[0]), "+f"(d[1]), "+f"(d[2]), "+f"(d[3])
        : "r"(a.x), "r"(a.y), "r"(a.z), "r"(a.w), "r"(b0), "r"(b1));
}

__device__ __forceinline__ void cp16(void* s, const void* g) {
    uint32_t sa = (uint32_t)__cvta_generic_to_shared(s);
    asm volatile("cp.async.cg.shared.global [%0], [%1], 16;\n" :: "r"(sa), "l"(g));
}
#define CPCOMMIT() asm volatile("cp.async.commit_group;\n")
#define CPW0() asm volatile("cp.async.wait_group 0;\n")
#define CPW1() asm volatile("cp.async.wait_group 1;\n")
#define CPW2() asm volatile("cp.async.wait_group 2;\n")

__device__ __forceinline__ float tanh_ap(float x) {
    float y; asm("tanh.approx.f32 %0, %1;" : "=f"(y) : "f"(x)); return y;
}
__device__ __forceinline__ float sig_ap(float x) { return 0.5f * tanh_ap(0.5f * x) + 0.5f; }

__device__ __forceinline__ uint32_t packh2(float lo, float hi) {
    __half2 h = __floats2half2_rn(lo, hi);
    return *(uint32_t*)&h;
}

// ---------------------------------------------------------------------------
// Prepass: W_hh [GG][HH] -> fp16 B-frag [j0 12][kc 48][ntpair 16][lane 32][4 u32]
// ---------------------------------------------------------------------------
__global__ void frag_whh_kernel(const float* __restrict__ W, __half* __restrict__ outh) {
    int idx = blockIdx.x * 256 + threadIdx.x;
    if (idx >= GG * HH) return;
    int r = idx / HH, k = idx - r * HH;
    int gate = r / HH;
    int jglob = r - gate * HH;
    int j0 = jglob >> 6;
    int ncol = gate * 64 + (jglob & 63);     // 0..255
    int kc = k >> 4, kl = k & 15;
    int ntpair = ncol >> 4, sub = (ncol >> 3) & 1, nloc = ncol & 7;
    int lane = nloc * 4 + ((kl & 7) >> 1);
    int reg = kl >> 3;
    size_t u32i = ((((size_t)j0 * KC + kc) * 16 + ntpair) * 32 + lane) * 4 + sub * 2 + reg;
    outh[u32i * 2 + (kl & 1)] = __float2half(W[idx]);
}

// ---------------------------------------------------------------------------
// Prepass: W_ih [GG][K] -> fp16 B-frag [n0 24][kc Kc][ntpair 8][lane 32][4 u32]
// Per (n0,kc) block = 1024 u32; total GG*Kc*16/2 u32.
// ---------------------------------------------------------------------------
__global__ void frag_wih_kernel(const float* __restrict__ W, __half* __restrict__ outh,
                                int K, int Kc) {
    int kb = Kc * 16;
    int idx = blockIdx.x * 256 + threadIdx.x;
    if (idx >= GG * kb) return;
    int r = idx / kb, k = idx - r * kb;
    int n0 = r >> 7, ncol = r & 127;
    int kc = k >> 4, kl = k & 15;
    int ntpair = ncol >> 4, sub = (ncol >> 3) & 1, nloc = ncol & 7;
    int lane = nloc * 4 + ((kl & 7) >> 1);
    int reg = kl >> 3;
    size_t u32i = ((((size_t)n0 * Kc + kc) * 8 + ntpair) * 32 + lane) * 4 + sub * 2 + reg;
    float v = (k < K) ? W[(size_t)r * K + k] : 0.f;
    outh[u32i * 2 + (kl & 1)] = __float2half(v);
}

// ---------------------------------------------------------------------------
__global__ void prep_bias(const float* __restrict__ bi, const float* __restrict__ bh,
                          float* __restrict__ bias) {
    int i = blockIdx.x * 256 + threadIdx.x;
    if (i < GG) bias[i] = bi[i] + bh[i];
}

__global__ void prep_state(uint32_t* __restrict__ hf, float* __restrict__ c) {
    int i = blockIdx.x * 256 + threadIdx.x;
    if (i == 0) g_bar = 0u;
    if (i < 196608) hf[i] = 0u;
    if (i < BB * HH) c[i] = 0.f;
}

// ---------------------------------------------------------------------------
// Input GEMM: xg[t][b][col] = bias[col] + A[m][:] . W[col][:],  m = b*TT + t
// CTA 128m x 128n, 8 warps (wm 4 x wn 2), warp 32m x 64n, fp16 m16n8k16.
// A either fp32 (layer 0: x) or fp16 (layers 1/2: hseq). Grid (n fastest).
// ---------------------------------------------------------------------------
__global__ __launch_bounds__(256) void gemm_in3(
    const float* __restrict__ Af, const __half* __restrict__ Ah,
    const uint32_t* __restrict__ Bf, const float* __restrict__ bias,
    __half* __restrict__ out, int K, int Kc, int a_half)
{
    __shared__ __align__(16) uint32_t As[2][1024];   // [mt 8][lane 32][reg 4]
    __shared__ __align__(16) uint32_t Bs[2][1024];   // [ntpair 8][lane 32][4]
    const int tid = threadIdx.x, lane = tid & 31, wid = tid >> 5;
    const int wm = wid >> 1, wn = wid & 1;
    const int n0 = blockIdx.x, m0 = blockIdx.y;
    const int g = lane >> 2, tg = lane & 3;

    float acc[2][8][4];
    #pragma unroll
    for (int i = 0; i < 2; i++)
        #pragma unroll
        for (int j = 0; j < 8; j++)
            #pragma unroll
            for (int k = 0; k < 4; k++) acc[i][j][k] = 0.f;

    const int row = tid >> 1, kp = (tid & 1) * 8;
    const int mt = row >> 4, mloc = row & 15;
    const int regbase = (kp >> 3) * 2 + (mloc >> 3);
    const uint32_t* Bbase = Bf + (size_t)n0 * Kc * 1024;

    uint32_t av[4];
    auto ldgA = [&](int kc) {
        int k0 = kc * 16;
        if (a_half) {
            const __half* src = Ah + (size_t)(m0 * 128 + row) * K + k0 + kp;
            uint4 v = *(const uint4*)src;   // 8 halves, already (lo,hi) k-pairs
            av[0] = v.x; av[1] = v.y; av[2] = v.z; av[3] = v.w;
        } else {
            float t0[4] = {0, 0, 0, 0}, t1[4] = {0, 0, 0, 0};
            const float* src = Af + (size_t)(m0 * 128 + row) * K + k0 + kp;
            if (k0 + kp < K)     *(float4*)t0 = *(const float4*)src;
            if (k0 + kp + 4 < K) *(float4*)t1 = *(const float4*)(src + 4);
            av[0] = packh2(t0[0], t0[1]); av[1] = packh2(t0[2], t0[3]);
            av[2] = packh2(t1[0], t1[1]); av[3] = packh2(t1[2], t1[3]);
        }
    };
    auto stsA = [&](int buf) {
        #pragma unroll
        for (int i = 0; i < 4; i++)
            As[buf][(mt * 32 + (mloc & 7) * 4 + i) * 4 + regbase] = av[i];
    };
    auto cpB = [&](int buf, int kc) {
        const uint32_t* src = Bbase + (size_t)kc * 1024;
        cp16(&Bs[buf][tid * 4], src + tid * 4);   // 256 threads * 4 u32 = 1024
    };

    ldgA(0); cpB(0, 0); CPCOMMIT();
    stsA(0);
    CPW0();
    __syncthreads();

    for (int kc = 0; kc < Kc; kc++) {
        int cur = kc & 1, nxt = cur ^ 1;
        if (kc + 1 < Kc) { cpB(nxt, kc + 1); CPCOMMIT(); ldgA(kc + 1); }
        uint4 af[2];
        #pragma unroll
        for (int mti = 0; mti < 2; mti++)
            af[mti] = *(const uint4*)&As[cur][((2 * wm + mti) * 32 + lane) * 4];
        #pragma unroll
        for (int p = 0; p < 4; p++) {
            uint4 bq = *(const uint4*)&Bs[cur][((wn * 4 + p) * 32 + lane) * 4];
            mma16(acc[0][2 * p], af[0], bq.x, bq.y);
            mma16(acc[1][2 * p], af[1], bq.x, bq.y);
            mma16(acc[0][2 * p + 1], af[0], bq.z, bq.w);
            mma16(acc[1][2 * p + 1], af[1], bq.z, bq.w);
        }
        if (kc + 1 < Kc) { stsA(nxt); CPW0(); }
        __syncthreads();
    }

    #pragma unroll
    for (int mti = 0; mti < 2; mti++)
        #pragma unroll
        for (int nt = 0; nt < 8; nt++)
            #pragma unroll
            for (int rh = 0; rh < 2; rh++) {      // rh: row-half (g vs g+8)
                int rrow = wm * 32 + mti * 16 + g + rh * 8;
                int m = m0 * 128 + rrow;
                int col = n0 * 128 + wn * 64 + nt * 8 + 2 * tg;
                int b = m / TT, t = m - b * TT;
                float v0 = acc[mti][nt][rh * 2 + 0] + __ldg(&bias[col]);
                float v1 = acc[mti][nt][rh * 2 + 1] + __ldg(&bias[col + 1]);
                __half2 hv = __floats2half2_rn(v0, v1);
                *(__half2*)&out[((size_t)t * BB + b) * GG + col] = hv;
            }
}

// ---------------------------------------------------------------------------
// Persistent LSTM layer (fp16 operands, fp32 accum). 96 CTAs (8 m x 12 j),
// 4-stage cp.async pipeline, grid barrier between steps.
// dyn smem: stages 4*10240B | gsm 33280B | fs 8192B = 82432B
// ---------------------------------------------------------------------------
__global__ __launch_bounds__(256, 1) void lstm_persist(
    const uint32_t* __restrict__ Wf, const __half* __restrict__ xg,
    uint32_t* __restrict__ hfA, uint32_t* __restrict__ hfB,
    float* __restrict__ cst, __half* __restrict__ hseq, int seq_all)
{
    extern __shared__ __align__(16) char smc[];
    float* gsm = (float*)(smc + 40960);
    __half* fsh = (__half*)(smc + 40960 + 33280);
    uint32_t* fsu = (uint32_t*)fsh;

    const int tid = threadIdx.x, lane = tid & 31, wid = tid >> 5;
    const int wm = wid >> 2, wn = wid & 3;
    const int m0 = blockIdx.x & 7, j0 = blockIdx.x >> 3;
    const int g = lane >> 2, tg = lane & 3;
    const uint32_t* Bb = Wf + (size_t)j0 * (KC * 2048);

    for (int t = 0; t < TT; t++) {
        const uint32_t* Ain = ((t & 1) ? hfB : hfA) + (size_t)m0 * (KC * 512);
        uint32_t* Hout = (t & 1) ? hfA : hfB;

        auto cpAB = [&](int kc) {
            uint32_t* dst = (uint32_t*)(smc + (kc & 3) * 10240);
            if (tid < 128) cp16(&dst[tid * 4], Ain + (size_t)kc * 512 + tid * 4);
            const uint32_t* b = Bb + (size_t)kc * 2048;
            cp16(&dst[512 + tid * 4], b + tid * 4);
            cp16(&dst[512 + (tid + 256) * 4], b + (tid + 256) * 4);
        };

        float acc[2][8][4];
        #pragma unroll
        for (int i = 0; i < 2; i++)
            #pragma unroll
            for (int j = 0; j < 8; j++)
                #pragma unroll
                for (int k = 0; k < 4; k++) acc[i][j][k] = 0.f;

        cpAB(0); CPCOMMIT();
        cpAB(1); CPCOMMIT();
        cpAB(2); CPCOMMIT();

        for (int kc = 0; kc < KC; kc++) {
            if (kc < KC - 2) CPW2(); else if (kc == KC - 2) CPW1(); else CPW0();
            __syncthreads();
            if (kc + 3 < KC) { cpAB(kc + 3); CPCOMMIT(); }
            const uint32_t* stg = (const uint32_t*)(smc + (kc & 3) * 10240);
            uint4 af[2];
            #pragma unroll
            for (int mti = 0; mti < 2; mti++)
                af[mti] = *(const uint4*)&stg[((2 * wm + mti) * 32 + lane) * 4];
            #pragma unroll
            for (int p = 0; p < 4; p++) {
                uint4 bq = *(const uint4*)&stg[512 + ((wn * 4 + p) * 32 + lane) * 4];
                mma16(acc[0][2 * p], af[0], bq.x, bq.y);
                mma16(acc[1][2 * p], af[1], bq.x, bq.y);
                mma16(acc[0][2 * p + 1], af[0], bq.z, bq.w);
                mma16(acc[1][2 * p + 1], af[1], bq.z, bq.w);
            }
        }

        // ---- epilogue: two 32-row passes through smem gate transpose ----
        for (int p = 0; p < 2; p++) {
            __syncthreads();
            if (wm == p) {
                #pragma unroll
                for (int mti = 0; mti < 2; mti++)
                    #pragma unroll
                    for (int nt = 0; nt < 8; nt++)
                        #pragma unroll
                        for (int r2 = 0; r2 < 4; r2++) {
                            int mi = mti * 16 + g + ((r2 & 2) ? 8 : 0);
                            int cj = nt * 8 + 2 * tg + (r2 & 1);
                            gsm[mi * 260 + wn * 65 + cj] = acc[mti][nt][r2];
                        }
            }
            __syncthreads();
            int cj = tid & 63, r0 = tid >> 6;
            #pragma unroll
            for (int r = r0; r < 32; r += 4) {
                int bl = p * 32 + r;
                int b = m0 * 64 + bl;
                int j = j0 * 64 + cj;
                const __half* xh = xg + ((size_t)t * BB + b) * GG + j;
                float pi = gsm[r * 260 + 0 * 65 + cj] + __half2float(xh[0]);
                float pf = gsm[r * 260 + 1 * 65 + cj] + __half2float(xh[HH]);
                float pg = gsm[r * 260 + 2 * 65 + cj] + __half2float(xh[2 * HH]);
                float po = gsm[r * 260 + 3 * 65 + cj] + __half2float(xh[3 * HH]);
                float iv = sig_ap(pi), fv = sig_ap(pf), gv = tanh_ap(pg), ov = sig_ap(po);
                size_t ci = (size_t)b * HH + j;
                float cn = fv * cst[ci] + iv * gv;
                cst[ci] = cn;
                float hn = ov * tanh_ap(cn);
                if (seq_all || t == TT - 1)
                    hseq[((size_t)b * TT + t) * HH + j] = __float2half(hn);
                // stage h into fp16 A-frag layout
                int q = cj >> 4, kl = cj & 15;
                int mt = bl >> 4, mloc = bl & 15;
                int lf = (mloc & 7) * 4 + ((kl & 7) >> 1);
                int reg = (kl >> 3) * 2 + (mloc >> 3);
                fsh[((((q * 4 + mt) * 32 + lf) * 4) + reg) * 2 + (kl & 1)] = __float2half(hn);
            }
        }
        __syncthreads();
        if (t < TT - 1) {
            // coalesced frag store (2048 u32)
            size_t fb = ((size_t)m0 * KC + (size_t)j0 * 4) * 512;
            #pragma unroll
            for (int i = 0; i < 2; i++) {
                int e = tid + i * 256;   // uint4 index 0..511
                *(uint4*)&Hout[fb + e * 4] = *(const uint4*)&fsu[e * 4];
            }
            __threadfence();
            __syncthreads();
            if (tid == 0) {
                atomicAdd(&g_bar, 1u);
                unsigned target = (unsigned)NCTA * (unsigned)(t + 1);
                while (true) {
                    unsigned v;
                    asm volatile("ld.global.acquire.gpu.u32 %0, [%1];"
                                 : "=r"(v) : "l"(&g_bar));
                    if (v >= target) break;
                    __nanosleep(32);
                }
            }
            __syncthreads();
            __threadfence();
        }
    }
}

// ---------------------------------------------------------------------------
// Projection + L2 normalize from hseq[:, T-1, :]
// ---------------------------------------------------------------------------
__global__ __launch_bounds__(256) void proj_kernel(
    const __half* __restrict__ hseq, const float* __restrict__ pw,
    const float* __restrict__ pb, float* __restrict__ out)
{
    __shared__ float hs[8][HH];
    __shared__ float red[256];
    const int b0 = blockIdx.x * 8;
    const int tid = threadIdx.x;

    for (int i = tid; i < 8 * HH; i += 256) {
        int r = i / HH, k = i % HH;
        hs[r][k] = __half2float(hseq[((size_t)(b0 + r) * TT + (TT - 1)) * HH + k]);
    }
    __syncthreads();

    float s[8];
    float bias = pb[tid];
    #pragma unroll
    for (int r = 0; r < 8; r++) s[r] = bias;
    const float* w = pw + (size_t)tid * HH;
    for (int k = 0; k < HH; k++) {
        float wv = w[k];
        #pragma unroll
        for (int r = 0; r < 8; r++) s[r] += wv * hs[r][k];
    }

    for (int r = 0; r < 8; r++) {
        red[tid] = s[r] * s[r];
        __syncthreads();
        for (int off = 128; off > 0; off >>= 1) {
            if (tid < off) red[tid] += red[tid + off];
            __syncthreads();
        }
        float rn = rsqrtf(red[0]);
        __syncthreads();
        out[(size_t)(b0 + r) * PR + tid] = s[r] * rn;
    }
}

// ---------------------------------------------------------------------------
// host
// ---------------------------------------------------------------------------
extern "C" void kernel_launch(void* const* d_in, const int* in_sizes, int n_in,
                              void* d_out, int out_size)
{
    const float* x = (const float*)d_in[0];
    const float* w_ih[3] = {(const float*)d_in[1], (const float*)d_in[5], (const float*)d_in[9]};
    const float* w_hh[3] = {(const float*)d_in[2], (const float*)d_in[6], (const float*)d_in[10]};
    const float* b_ih[3] = {(const float*)d_in[3], (const float*)d_in[7], (const float*)d_in[11]};
    const float* b_hh[3] = {(const float*)d_in[4], (const float*)d_in[8], (const float*)d_in[12]};
    const float* pw = (const float*)d_in[13];
    const float* pb = (const float*)d_in[14];
    float* out = (float*)d_out;

    cudaFuncSetAttribute(lstm_persist, cudaFuncAttributeMaxDynamicSharedMemorySize, 82944);

    __half *xg_p, *hs0_p, *hs1_p;
    uint32_t *hf_p, *whhf_p, *wihf_p;
    float *c_p, *bias_p;
    cudaGetSymbolAddress((void**)&xg_p, g_xg);
    cudaGetSymbolAddress((void**)&hs0_p, g_hseq0);
    cudaGetSymbolAddress((void**)&hs1_p, g_hseq1);
    cudaGetSymbolAddress((void**)&hf_p, g_hfrag);
    cudaGetSymbolAddress((void**)&c_p, g_c);
    cudaGetSymbolAddress((void**)&whhf_p, g_whhf);
    cudaGetSymbolAddress((void**)&wihf_p, g_wihf);
    cudaGetSymbolAddress((void**)&bias_p, g_bias);
    uint32_t* hf0 = hf_p;
    uint32_t* hf1 = hf_p + 196608;

    const __half* inH[3] = {nullptr, hs0_p, hs1_p};
    __half* outH[3] = {hs0_p, hs1_p, hs0_p};
    int Ks[3] = {NM, HH, HH};
    int Kcs[3] = {3, KC, KC};

    for (int l = 0; l < 3; l++) {
        int nW = GG * Kcs[l] * 16;
        frag_wih_kernel<<<(nW + 255) / 256, 256>>>(w_ih[l], (__half*)wihf_p, Ks[l], Kcs[l]);
        frag_whh_kernel<<<(GG * HH + 255) / 256, 256>>>(w_hh[l], (__half*)whhf_p);
        prep_bias<<<(GG + 255) / 256, 256>>>(b_ih[l], b_hh[l], bias_p);
        gemm_in3<<<dim3(GG / 128, (BB * TT) / 128), 256>>>(
            (l == 0) ? x : nullptr, inH[l], wihf_p, bias_p, xg_p, Ks[l], Kcs[l],
            (l == 0) ? 0 : 1);
        prep_state<<<(BB * HH + 255) / 256, 256>>>(hf0, c_p);
        lstm_persist<<<NCTA, 256, 82944>>>(whhf_p, xg_p, hf0, hf1, c_p, outH[l],
                                           (l < 2) ? 1 : 0);
    }
    proj_kernel<<<BB / 8, 256>>>(hs0_p, pw, pb, out);
}

// round 9
// speedup vs baseline: 4.4875x; 1.2612x over previous
#include <cuda_runtime.h>
#include <cuda_fp16.h>
#include <cstdint>
#include <math.h>

#define BB 512
#define TT 180
#define NM 40
#define HH 768
#define GG 3072   // 4*HH
#define PR 256
#define KC 48     // HH/16
#define NC32 24   // HH/32
#define NCTA 96

// ---- static device scratch ----
__device__ __half g_xg[(size_t)TT * BB * GG];        // [t][b][gcol] fp16
__device__ __half g_hseq0[(size_t)BB * TT * HH];
__device__ __half g_hseq1[(size_t)BB * TT * HH];
__device__ uint32_t g_hfrag[2 * 196608];             // A-frag fp16 h (ping-pong): [m0 8][kc 48][mt 4][lane 32][reg 4]
__device__ uint32_t g_whhf[1179648];                 // B-frag fp16 W_hh: [j0 12][kc 48][ntpair 16][lane 32][4]
__device__ uint32_t g_wihf[1179648];                 // B-frag fp16 W_ih: [n0 24][kc Kc][ntpair 8][lane 32][4]
__device__ float g_bias[GG];
__device__ unsigned g_bar;

__device__ __forceinline__ void mma16(float* d, uint4 a, uint32_t b0, uint32_t b1) {
    asm volatile(
        "mma.sync.aligned.m16n8k16.row.col.f32.f16.f16.f32 "
        "{%0,%1,%2,%3}, {%4,%5,%6,%7}, {%8,%9}, {%0,%1,%2,%3};\n"
        : "+f"(d[0]), "+f"(d[1]), "+f"(d[2]), "+f"(d[3])
        : "r"(a.x), "r"(a.y), "r"(a.z), "r"(a.w), "r"(b0), "r"(b1));
}

__device__ __forceinline__ void cp16(void* s, const void* g) {
    uint32_t sa = (uint32_t)__cvta_generic_to_shared(s);
    asm volatile("cp.async.cg.shared.global [%0], [%1], 16;\n" :: "r"(sa), "l"(g));
}
#define CPCOMMIT() asm volatile("cp.async.commit_group;\n")
#define CPW0() asm volatile("cp.async.wait_group 0;\n")
#define CPW1() asm volatile("cp.async.wait_group 1;\n")

__device__ __forceinline__ float tanh_ap(float x) {
    float y; asm("tanh.approx.f32 %0, %1;" : "=f"(y) : "f"(x)); return y;
}
__device__ __forceinline__ float sig_ap(float x) { return 0.5f * tanh_ap(0.5f * x) + 0.5f; }

__device__ __forceinline__ uint32_t packh2(float lo, float hi) {
    __half2 h = __floats2half2_rn(lo, hi);
    return *(uint32_t*)&h;
}

// ---------------------------------------------------------------------------
// Prepass: W_hh [GG][HH] -> fp16 B-frag [j0 12][kc 48][ntpair 16][lane 32][4 u32]
// ---------------------------------------------------------------------------
__global__ void frag_whh_kernel(const float* __restrict__ W, __half* __restrict__ outh) {
    int idx = blockIdx.x * 256 + threadIdx.x;
    if (idx >= GG * HH) return;
    int r = idx / HH, k = idx - r * HH;
    int gate = r / HH;
    int jglob = r - gate * HH;
    int j0 = jglob >> 6;
    int ncol = gate * 64 + (jglob & 63);     // 0..255
    int kc = k >> 4, kl = k & 15;
    int ntpair = ncol >> 4, sub = (ncol >> 3) & 1, nloc = ncol & 7;
    int lane = nloc * 4 + ((kl & 7) >> 1);
    int reg = kl >> 3;
    size_t u32i = ((((size_t)j0 * KC + kc) * 16 + ntpair) * 32 + lane) * 4 + sub * 2 + reg;
    outh[u32i * 2 + (kl & 1)] = __float2half(W[idx]);
}

// ---------------------------------------------------------------------------
// Prepass: W_ih [GG][K] -> fp16 B-frag [n0 24][kc Kc][ntpair 8][lane 32][4 u32]
// ---------------------------------------------------------------------------
__global__ void frag_wih_kernel(const float* __restrict__ W, __half* __restrict__ outh,
                                int K, int Kc) {
    int kb = Kc * 16;
    int idx = blockIdx.x * 256 + threadIdx.x;
    if (idx >= GG * kb) return;
    int r = idx / kb, k = idx - r * kb;
    int n0 = r >> 7, ncol = r & 127;
    int kc = k >> 4, kl = k & 15;
    int ntpair = ncol >> 4, sub = (ncol >> 3) & 1, nloc = ncol & 7;
    int lane = nloc * 4 + ((kl & 7) >> 1);
    int reg = kl >> 3;
    size_t u32i = ((((size_t)n0 * Kc + kc) * 8 + ntpair) * 32 + lane) * 4 + sub * 2 + reg;
    float v = (k < K) ? W[(size_t)r * K + k] : 0.f;
    outh[u32i * 2 + (kl & 1)] = __float2half(v);
}

// ---------------------------------------------------------------------------
__global__ void prep_bias(const float* __restrict__ bi, const float* __restrict__ bh,
                          float* __restrict__ bias) {
    int i = blockIdx.x * 256 + threadIdx.x;
    if (i < GG) bias[i] = bi[i] + bh[i];
}

__global__ void prep_state(uint32_t* __restrict__ hf) {
    int i = blockIdx.x * 256 + threadIdx.x;
    if (i == 0) g_bar = 0u;
    if (i < 196608) hf[i] = 0u;
}

// ---------------------------------------------------------------------------
// Input GEMM: xg[t][b][col] = bias[col] + A[m][:] . W[col][:],  m = b*TT + t
// CTA 128m x 128n, 8 warps (wm 4 x wn 2), warp 32m x 64n, fp16 m16n8k16.
// Dynamic smem: As 8192B | Bs 8192B | staging 32768B  = 49152B
// ---------------------------------------------------------------------------
__global__ __launch_bounds__(256) void gemm_in3(
    const float* __restrict__ Af, const __half* __restrict__ Ah,
    const uint32_t* __restrict__ Bf, const float* __restrict__ bias,
    __half* __restrict__ out, int K, int Kc, int a_half)
{
    extern __shared__ __align__(16) char smd[];
    uint32_t (*As)[1024] = (uint32_t(*)[1024])smd;            // 2 x 1024 u32
    uint32_t (*Bs)[1024] = (uint32_t(*)[1024])(smd + 8192);   // 2 x 1024 u32
    __half* stg = (__half*)(smd + 16384);                      // 128 x 128 halves

    const int tid = threadIdx.x, lane = tid & 31, wid = tid >> 5;
    const int wm = wid >> 1, wn = wid & 1;
    const int n0 = blockIdx.x, m0 = blockIdx.y;
    const int g = lane >> 2, tg = lane & 3;

    float acc[2][8][4];
    #pragma unroll
    for (int i = 0; i < 2; i++)
        #pragma unroll
        for (int j = 0; j < 8; j++)
            #pragma unroll
            for (int k = 0; k < 4; k++) acc[i][j][k] = 0.f;

    const int row = tid >> 1, kp = (tid & 1) * 8;
    const int mt = row >> 4, mloc = row & 15;
    const int regbase = (kp >> 3) * 2 + (mloc >> 3);
    const uint32_t* Bbase = Bf + (size_t)n0 * Kc * 1024;

    uint32_t av[4];
    auto ldgA = [&](int kc) {
        int k0 = kc * 16;
        if (a_half) {
            const __half* src = Ah + (size_t)(m0 * 128 + row) * K + k0 + kp;
            uint4 v = *(const uint4*)src;
            av[0] = v.x; av[1] = v.y; av[2] = v.z; av[3] = v.w;
        } else {
            float t0[4] = {0, 0, 0, 0}, t1[4] = {0, 0, 0, 0};
            const float* src = Af + (size_t)(m0 * 128 + row) * K + k0 + kp;
            if (k0 + kp < K)     *(float4*)t0 = *(const float4*)src;
            if (k0 + kp + 4 < K) *(float4*)t1 = *(const float4*)(src + 4);
            av[0] = packh2(t0[0], t0[1]); av[1] = packh2(t0[2], t0[3]);
            av[2] = packh2(t1[0], t1[1]); av[3] = packh2(t1[2], t1[3]);
        }
    };
    auto stsA = [&](int buf) {
        #pragma unroll
        for (int i = 0; i < 4; i++)
            As[buf][(mt * 32 + (mloc & 7) * 4 + i) * 4 + regbase] = av[i];
    };
    auto cpB = [&](int buf, int kc) {
        const uint32_t* src = Bbase + (size_t)kc * 1024;
        cp16(&Bs[buf][tid * 4], src + tid * 4);
    };

    ldgA(0); cpB(0, 0); CPCOMMIT();
    stsA(0);
    CPW0();
    __syncthreads();

    for (int kc = 0; kc < Kc; kc++) {
        int cur = kc & 1, nxt = cur ^ 1;
        if (kc + 1 < Kc) { cpB(nxt, kc + 1); CPCOMMIT(); ldgA(kc + 1); }
        uint4 af[2];
        #pragma unroll
        for (int mti = 0; mti < 2; mti++)
            af[mti] = *(const uint4*)&As[cur][((2 * wm + mti) * 32 + lane) * 4];
        #pragma unroll
        for (int p = 0; p < 4; p++) {
            uint4 bq = *(const uint4*)&Bs[cur][((wn * 4 + p) * 32 + lane) * 4];
            mma16(acc[0][2 * p], af[0], bq.x, bq.y);
            mma16(acc[1][2 * p], af[1], bq.x, bq.y);
            mma16(acc[0][2 * p + 1], af[0], bq.z, bq.w);
            mma16(acc[1][2 * p + 1], af[1], bq.z, bq.w);
        }
        if (kc + 1 < Kc) { stsA(nxt); CPW0(); }
        __syncthreads();
    }

    // epilogue: stage tile in smem (add bias), then coalesced 16B row bursts
    #pragma unroll
    for (int mti = 0; mti < 2; mti++)
        #pragma unroll
        for (int nt = 0; nt < 8; nt++)
            #pragma unroll
            for (int rh = 0; rh < 2; rh++) {
                int rrow = wm * 32 + mti * 16 + g + rh * 8;
                int coll = wn * 64 + nt * 8 + 2 * tg;
                float v0 = acc[mti][nt][rh * 2 + 0] + __ldg(&bias[n0 * 128 + coll]);
                float v1 = acc[mti][nt][rh * 2 + 1] + __ldg(&bias[n0 * 128 + coll + 1]);
                *(__half2*)&stg[rrow * 128 + coll] = __floats2half2_rn(v0, v1);
            }
    __syncthreads();
    #pragma unroll
    for (int i = 0; i < 8; i++) {
        int unit = tid + i * 256;            // 0..2047 (16B units)
        int rrow = unit >> 4, u = unit & 15;
        int m = m0 * 128 + rrow;
        int b = m / TT, t = m - b * TT;
        __half* dst = &out[((size_t)t * BB + b) * GG + n0 * 128];
        *(uint4*)((char*)dst + u * 16) = *(const uint4*)((char*)&stg[rrow * 128] + u * 16);
    }
}

// ---------------------------------------------------------------------------
// Persistent LSTM layer (fp16 operands, fp32 accum). 96 CTAs (8 m x 12 j).
// K-chunk 32 (2 x k16 blocks per stage), 3 stages, grid barrier per step.
// Cell state lives in registers (fixed (b,j) ownership across all steps).
// dyn smem: stages 3*20480B | gsm 33280B | fs 8192B = 102912B
// ---------------------------------------------------------------------------
__global__ __launch_bounds__(256, 1) void lstm_persist(
    const uint32_t* __restrict__ Wf, const __half* __restrict__ xg,
    uint32_t* __restrict__ hfA, uint32_t* __restrict__ hfB,
    __half* __restrict__ hseq, int seq_all)
{
    extern __shared__ __align__(16) char smc[];
    float* gsm = (float*)(smc + 61440);
    __half* fsh = (__half*)(smc + 61440 + 33280);
    uint32_t* fsu = (uint32_t*)fsh;

    const int tid = threadIdx.x, lane = tid & 31, wid = tid >> 5;
    const int wm = wid >> 2, wn = wid & 3;
    const int m0 = blockIdx.x & 7, j0 = blockIdx.x >> 3;
    const int g = lane >> 2, tg = lane & 3;
    const uint32_t* Bb = Wf + (size_t)j0 * (KC * 2048);

    float creg[2][8];   // cell state, fixed ownership: [p][(r-r0)/4]
    #pragma unroll
    for (int p = 0; p < 2; p++)
        #pragma unroll
        for (int i = 0; i < 8; i++) creg[p][i] = 0.f;

    for (int t = 0; t < TT; t++) {
        const uint32_t* Ain = ((t & 1) ? hfB : hfA) + (size_t)m0 * (KC * 512);
        uint32_t* Hout = (t & 1) ? hfA : hfB;

        // one chunk32 = 1024 u32 A + 4096 u32 B, contiguous in both sources
        auto cpAB = [&](int kcc) {
            uint32_t* dst = (uint32_t*)(smc + (kcc % 3) * 20480);
            cp16(&dst[tid * 4], Ain + (size_t)kcc * 1024 + tid * 4);
            const uint32_t* b = Bb + (size_t)kcc * 4096;
            #pragma unroll
            for (int i = 0; i < 4; i++)
                cp16(&dst[1024 + (tid + i * 256) * 4], b + (tid + i * 256) * 4);
        };

        float acc[2][8][4];
        #pragma unroll
        for (int i = 0; i < 2; i++)
            #pragma unroll
            for (int j = 0; j < 8; j++)
                #pragma unroll
                for (int k = 0; k < 4; k++) acc[i][j][k] = 0.f;

        cpAB(0); CPCOMMIT();
        cpAB(1); CPCOMMIT();

        for (int kcc = 0; kcc < NC32; kcc++) {
            if (kcc < NC32 - 1) CPW1(); else CPW0();
            __syncthreads();
            if (kcc + 2 < NC32) { cpAB(kcc + 2); CPCOMMIT(); }
            const uint32_t* stgb = (const uint32_t*)(smc + (kcc % 3) * 20480);
            #pragma unroll
            for (int half = 0; half < 2; half++) {
                const uint32_t* sA = stgb + half * 512;
                const uint32_t* sB = stgb + 1024 + half * 2048;
                uint4 af[2];
                #pragma unroll
                for (int mti = 0; mti < 2; mti++)
                    af[mti] = *(const uint4*)&sA[((2 * wm + mti) * 32 + lane) * 4];
                #pragma unroll
                for (int p = 0; p < 4; p++) {
                    uint4 bq = *(const uint4*)&sB[((wn * 4 + p) * 32 + lane) * 4];
                    mma16(acc[0][2 * p], af[0], bq.x, bq.y);
                    mma16(acc[1][2 * p], af[1], bq.x, bq.y);
                    mma16(acc[0][2 * p + 1], af[0], bq.z, bq.w);
                    mma16(acc[1][2 * p + 1], af[1], bq.z, bq.w);
                }
            }
        }

        // ---- epilogue: two 32-row passes through smem gate transpose ----
        for (int p = 0; p < 2; p++) {
            __syncthreads();
            if (wm == p) {
                #pragma unroll
                for (int mti = 0; mti < 2; mti++)
                    #pragma unroll
                    for (int nt = 0; nt < 8; nt++)
                        #pragma unroll
                        for (int r2 = 0; r2 < 4; r2++) {
                            int mi = mti * 16 + g + ((r2 & 2) ? 8 : 0);
                            int cj = nt * 8 + 2 * tg + (r2 & 1);
                            gsm[mi * 260 + wn * 65 + cj] = acc[mti][nt][r2];
                        }
            }
            __syncthreads();
            int cj = tid & 63, r0 = tid >> 6;
            #pragma unroll
            for (int i = 0; i < 8; i++) {
                int r = r0 + 4 * i;
                int bl = p * 32 + r;
                int b = m0 * 64 + bl;
                int j = j0 * 64 + cj;
                const __half* xh = xg + ((size_t)t * BB + b) * GG + j;
                float pi = gsm[r * 260 + 0 * 65 + cj] + __half2float(xh[0]);
                float pf = gsm[r * 260 + 1 * 65 + cj] + __half2float(xh[HH]);
                float pg = gsm[r * 260 + 2 * 65 + cj] + __half2float(xh[2 * HH]);
                float po = gsm[r * 260 + 3 * 65 + cj] + __half2float(xh[3 * HH]);
                float iv = sig_ap(pi), fv = sig_ap(pf), gv = tanh_ap(pg), ov = sig_ap(po);
                float cn = fv * creg[p][i] + iv * gv;
                creg[p][i] = cn;
                float hn = ov * tanh_ap(cn);
                if (seq_all || t == TT - 1)
                    hseq[((size_t)b * TT + t) * HH + j] = __float2half(hn);
                // stage h into fp16 A-frag layout
                int q = cj >> 4, kl = cj & 15;
                int mt = bl >> 4, mloc = bl & 15;
                int lf = (mloc & 7) * 4 + ((kl & 7) >> 1);
                int reg = (kl >> 3) * 2 + (mloc >> 3);
                fsh[((((q * 4 + mt) * 32 + lf) * 4) + reg) * 2 + (kl & 1)] = __float2half(hn);
            }
        }
        __syncthreads();
        if (t < TT - 1) {
            // coalesced frag store (2048 u32)
            size_t fb = ((size_t)m0 * KC + (size_t)j0 * 4) * 512;
            #pragma unroll
            for (int i = 0; i < 2; i++) {
                int e = tid + i * 256;
                *(uint4*)&Hout[fb + e * 4] = *(const uint4*)&fsu[e * 4];
            }
            __threadfence();
            __syncthreads();
            if (tid == 0) {
                atomicAdd(&g_bar, 1u);
                unsigned target = (unsigned)NCTA * (unsigned)(t + 1);
                while (true) {
                    unsigned v;
                    asm volatile("ld.global.acquire.gpu.u32 %0, [%1];"
                                 : "=r"(v) : "l"(&g_bar));
                    if (v >= target) break;
                    __nanosleep(16);
                }
            }
            __syncthreads();
        }
    }
}

// ---------------------------------------------------------------------------
// Projection + L2 normalize from hseq[:, T-1, :]
// ---------------------------------------------------------------------------
__global__ __launch_bounds__(256) void proj_kernel(
    const __half* __restrict__ hseq, const float* __restrict__ pw,
    const float* __restrict__ pb, float* __restrict__ out)
{
    __shared__ float hs[8][HH];
    __shared__ float red[256];
    const int b0 = blockIdx.x * 8;
    const int tid = threadIdx.x;

    for (int i = tid; i < 8 * HH; i += 256) {
        int r = i / HH, k = i % HH;
        hs[r][k] = __half2float(hseq[((size_t)(b0 + r) * TT + (TT - 1)) * HH + k]);
    }
    __syncthreads();

    float s[8];
    float bias = pb[tid];
    #pragma unroll
    for (int r = 0; r < 8; r++) s[r] = bias;
    const float* w = pw + (size_t)tid * HH;
    for (int k = 0; k < HH; k++) {
        float wv = w[k];
        #pragma unroll
        for (int r = 0; r < 8; r++) s[r] += wv * hs[r][k];
    }

    for (int r = 0; r < 8; r++) {
        red[tid] = s[r] * s[r];
        __syncthreads();
        for (int off = 128; off > 0; off >>= 1) {
            if (tid < off) red[tid] += red[tid + off];
            __syncthreads();
        }
        float rn = rsqrtf(red[0]);
        __syncthreads();
        out[(size_t)(b0 + r) * PR + tid] = s[r] * rn;
    }
}

// ---------------------------------------------------------------------------
// host
// ---------------------------------------------------------------------------
extern "C" void kernel_launch(void* const* d_in, const int* in_sizes, int n_in,
                              void* d_out, int out_size)
{
    const float* x = (const float*)d_in[0];
    const float* w_ih[3] = {(const float*)d_in[1], (const float*)d_in[5], (const float*)d_in[9]};
    const float* w_hh[3] = {(const float*)d_in[2], (const float*)d_in[6], (const float*)d_in[10]};
    const float* b_ih[3] = {(const float*)d_in[3], (const float*)d_in[7], (const float*)d_in[11]};
    const float* b_hh[3] = {(const float*)d_in[4], (const float*)d_in[8], (const float*)d_in[12]};
    const float* pw = (const float*)d_in[13];
    const float* pb = (const float*)d_in[14];
    float* out = (float*)d_out;

    cudaFuncSetAttribute(lstm_persist, cudaFuncAttributeMaxDynamicSharedMemorySize, 103424);
    cudaFuncSetAttribute(gemm_in3, cudaFuncAttributeMaxDynamicSharedMemorySize, 49152);

    __half *xg_p, *hs0_p, *hs1_p;
    uint32_t *hf_p, *whhf_p, *wihf_p;
    float *bias_p;
    cudaGetSymbolAddress((void**)&xg_p, g_xg);
    cudaGetSymbolAddress((void**)&hs0_p, g_hseq0);
    cudaGetSymbolAddress((void**)&hs1_p, g_hseq1);
    cudaGetSymbolAddress((void**)&hf_p, g_hfrag);
    cudaGetSymbolAddress((void**)&whhf_p, g_whhf);
    cudaGetSymbolAddress((void**)&wihf_p, g_wihf);
    cudaGetSymbolAddress((void**)&bias_p, g_bias);
    uint32_t* hf0 = hf_p;
    uint32_t* hf1 = hf_p + 196608;

    const __half* inH[3] = {nullptr, hs0_p, hs1_p};
    __half* outH[3] = {hs0_p, hs1_p, hs0_p};
    int Ks[3] = {NM, HH, HH};
    int Kcs[3] = {3, KC, KC};

    for (int l = 0; l < 3; l++) {
        int nW = GG * Kcs[l] * 16;
        frag_wih_kernel<<<(nW + 255) / 256, 256>>>(w_ih[l], (__half*)wihf_p, Ks[l], Kcs[l]);
        frag_whh_kernel<<<(GG * HH + 255) / 256, 256>>>(w_hh[l], (__half*)whhf_p);
        prep_bias<<<(GG + 255) / 256, 256>>>(b_ih[l], b_hh[l], bias_p);
        gemm_in3<<<dim3(GG / 128, (BB * TT) / 128), 256, 49152>>>(
            (l == 0) ? x : nullptr, inH[l], wihf_p, bias_p, xg_p, Ks[l], Kcs[l],
            (l == 0) ? 0 : 1);
        prep_state<<<(196608 + 255) / 256, 256>>>(hf0);
        lstm_persist<<<NCTA, 256, 103424>>>(whhf_p, xg_p, hf0, hf1, outH[l],
                                            (l < 2) ? 1 : 0);
    }
    proj_kernel<<<BB / 8, 256>>>(hs0_p, pw, pb, out);
}

// round 11
// speedup vs baseline: 5.7476x; 1.2808x over previous
#include <cuda_runtime.h>
#include <cuda_fp16.h>
#include <cstdint>
#include <math.h>

#define BB 512
#define TT 180
#define NM 40
#define HH 768
#define GG 3072   // 4*HH
#define PR 256
#define KC 48     // HH/16
#define NC32 24   // HH/32
#define NCTA 128  // 8 batch-tiles x 16 j-tiles

// ---- static device scratch ----
__device__ __half g_xg[(size_t)TT * BB * GG];        // [t][b][gcol] fp16
__device__ __half g_hseq0[(size_t)BB * TT * HH];
__device__ __half g_hseq1[(size_t)BB * TT * HH];
__device__ uint32_t g_hfrag[2 * 196608];             // A-frag fp16 h (ping-pong): [m0 8][kc 48][mt 4][lane 32][reg 4]
__device__ uint32_t g_whhf[1179648];                 // B-frag fp16 W_hh: [j0 16][kc 48][ntpair 12][lane 32][4]
__device__ uint32_t g_wihf[1179648];                 // B-frag fp16 W_ih: [n0 24][kc Kc][ntpair 8][lane 32][4]
__device__ float g_bias[GG];
__device__ unsigned g_bar;

__device__ __forceinline__ void mma16(float* d, uint4 a, uint32_t b0, uint32_t b1) {
    asm volatile(
        "mma.sync.aligned.m16n8k16.row.col.f32.f16.f16.f32 "
        "{%0,%1,%2,%3}, {%4,%5,%6,%7}, {%8,%9}, {%0,%1,%2,%3};\n"
        : "+f"(d[0]), "+f"(d[1]), "+f"(d[2]), "+f"(d[3])
        : "r"(a.x), "r"(a.y), "r"(a.z), "r"(a.w), "r"(b0), "r"(b1));
}

__device__ __forceinline__ void cp16(void* s, const void* g) {
    uint32_t sa = (uint32_t)__cvta_generic_to_shared(s);
    asm volatile("cp.async.cg.shared.global [%0], [%1], 16;\n" :: "r"(sa), "l"(g));
}
#define CPCOMMIT() asm volatile("cp.async.commit_group;\n")
#define CPW0() asm volatile("cp.async.wait_group 0;\n")
#define CPW1() asm volatile("cp.async.wait_group 1;\n")

__device__ __forceinline__ float tanh_ap(float x) {
    float y; asm("tanh.approx.f32 %0, %1;" : "=f"(y) : "f"(x)); return y;
}
__device__ __forceinline__ float sig_ap(float x) { return 0.5f * tanh_ap(0.5f * x) + 0.5f; }

__device__ __forceinline__ uint32_t packh2(float lo, float hi) {
    __half2 h = __floats2half2_rn(lo, hi);
    return *(uint32_t*)&h;
}

// ---------------------------------------------------------------------------
// Prepass: W_hh [GG][HH] -> fp16 B-frag [j0 16][kc 48][ntpair 12][lane 32][4 u32]
// j0 tiles of 48 hidden cols; ncol = gate*48 + cj (0..191).
// ---------------------------------------------------------------------------
__global__ void frag_whh_kernel(const float* __restrict__ W, __half* __restrict__ outh) {
    int idx = blockIdx.x * 256 + threadIdx.x;
    if (idx >= GG * HH) return;
    int r = idx / HH, k = idx - r * HH;
    int gate = r / HH;
    int jglob = r - gate * HH;
    int j0 = jglob / 48;
    int cj = jglob - j0 * 48;
    int ncol = gate * 48 + cj;               // 0..191
    int kc = k >> 4, kl = k & 15;
    int ntpair = ncol >> 4, sub = (ncol >> 3) & 1, nloc = ncol & 7;
    int lane = nloc * 4 + ((kl & 7) >> 1);
    int reg = kl >> 3;
    size_t u32i = ((((size_t)j0 * KC + kc) * 12 + ntpair) * 32 + lane) * 4 + sub * 2 + reg;
    outh[u32i * 2 + (kl & 1)] = __float2half(W[idx]);
}

// ---------------------------------------------------------------------------
// Prepass: W_ih [GG][K] -> fp16 B-frag [n0 24][kc Kc][ntpair 8][lane 32][4 u32]
// ---------------------------------------------------------------------------
__global__ void frag_wih_kernel(const float* __restrict__ W, __half* __restrict__ outh,
                                int K, int Kc) {
    int kb = Kc * 16;
    int idx = blockIdx.x * 256 + threadIdx.x;
    if (idx >= GG * kb) return;
    int r = idx / kb, k = idx - r * kb;
    int n0 = r >> 7, ncol = r & 127;
    int kc = k >> 4, kl = k & 15;
    int ntpair = ncol >> 4, sub = (ncol >> 3) & 1, nloc = ncol & 7;
    int lane = nloc * 4 + ((kl & 7) >> 1);
    int reg = kl >> 3;
    size_t u32i = ((((size_t)n0 * Kc + kc) * 8 + ntpair) * 32 + lane) * 4 + sub * 2 + reg;
    float v = (k < K) ? W[(size_t)r * K + k] : 0.f;
    outh[u32i * 2 + (kl & 1)] = __float2half(v);
}

// ---------------------------------------------------------------------------
__global__ void prep_bias(const float* __restrict__ bi, const float* __restrict__ bh,
                          float* __restrict__ bias) {
    int i = blockIdx.x * 256 + threadIdx.x;
    if (i < GG) bias[i] = bi[i] + bh[i];
}

__global__ void prep_state(uint32_t* __restrict__ hf) {
    int i = blockIdx.x * 256 + threadIdx.x;
    if (i == 0) g_bar = 0u;
    if (i < 196608) hf[i] = 0u;
}

// ---------------------------------------------------------------------------
// Input GEMM (unchanged — known good). CTA 128m x 128n, 8 warps.
// Dynamic smem: As 8192B | Bs 8192B | staging 32768B = 49152B
// ---------------------------------------------------------------------------
__global__ __launch_bounds__(256) void gemm_in3(
    const float* __restrict__ Af, const __half* __restrict__ Ah,
    const uint32_t* __restrict__ Bf, const float* __restrict__ bias,
    __half* __restrict__ out, int K, int Kc, int a_half)
{
    extern __shared__ __align__(16) char smd[];
    uint32_t (*As)[1024] = (uint32_t(*)[1024])smd;
    uint32_t (*Bs)[1024] = (uint32_t(*)[1024])(smd + 8192);
    __half* stg = (__half*)(smd + 16384);

    const int tid = threadIdx.x, lane = tid & 31, wid = tid >> 5;
    const int wm = wid >> 1, wn = wid & 1;
    const int n0 = blockIdx.x, m0 = blockIdx.y;
    const int g = lane >> 2, tg = lane & 3;

    float acc[2][8][4];
    #pragma unroll
    for (int i = 0; i < 2; i++)
        #pragma unroll
        for (int j = 0; j < 8; j++)
            #pragma unroll
            for (int k = 0; k < 4; k++) acc[i][j][k] = 0.f;

    const int row = tid >> 1, kp = (tid & 1) * 8;
    const int mt = row >> 4, mloc = row & 15;
    const int regbase = (kp >> 3) * 2 + (mloc >> 3);
    const uint32_t* Bbase = Bf + (size_t)n0 * Kc * 1024;

    uint32_t av[4];
    auto ldgA = [&](int kc) {
        int k0 = kc * 16;
        if (a_half) {
            const __half* src = Ah + (size_t)(m0 * 128 + row) * K + k0 + kp;
            uint4 v = *(const uint4*)src;
            av[0] = v.x; av[1] = v.y; av[2] = v.z; av[3] = v.w;
        } else {
            float t0[4] = {0, 0, 0, 0}, t1[4] = {0, 0, 0, 0};
            const float* src = Af + (size_t)(m0 * 128 + row) * K + k0 + kp;
            if (k0 + kp < K)     *(float4*)t0 = *(const float4*)src;
            if (k0 + kp + 4 < K) *(float4*)t1 = *(const float4*)(src + 4);
            av[0] = packh2(t0[0], t0[1]); av[1] = packh2(t0[2], t0[3]);
            av[2] = packh2(t1[0], t1[1]); av[3] = packh2(t1[2], t1[3]);
        }
    };
    auto stsA = [&](int buf) {
        #pragma unroll
        for (int i = 0; i < 4; i++)
            As[buf][(mt * 32 + (mloc & 7) * 4 + i) * 4 + regbase] = av[i];
    };
    auto cpB = [&](int buf, int kc) {
        const uint32_t* src = Bbase + (size_t)kc * 1024;
        cp16(&Bs[buf][tid * 4], src + tid * 4);
    };

    ldgA(0); cpB(0, 0); CPCOMMIT();
    stsA(0);
    CPW0();
    __syncthreads();

    for (int kc = 0; kc < Kc; kc++) {
        int cur = kc & 1, nxt = cur ^ 1;
        if (kc + 1 < Kc) { cpB(nxt, kc + 1); CPCOMMIT(); ldgA(kc + 1); }
        uint4 af[2];
        #pragma unroll
        for (int mti = 0; mti < 2; mti++)
            af[mti] = *(const uint4*)&As[cur][((2 * wm + mti) * 32 + lane) * 4];
        #pragma unroll
        for (int p = 0; p < 4; p++) {
            uint4 bq = *(const uint4*)&Bs[cur][((wn * 4 + p) * 32 + lane) * 4];
            mma16(acc[0][2 * p], af[0], bq.x, bq.y);
            mma16(acc[1][2 * p], af[1], bq.x, bq.y);
            mma16(acc[0][2 * p + 1], af[0], bq.z, bq.w);
            mma16(acc[1][2 * p + 1], af[1], bq.z, bq.w);
        }
        if (kc + 1 < Kc) { stsA(nxt); CPW0(); }
        __syncthreads();
    }

    #pragma unroll
    for (int mti = 0; mti < 2; mti++)
        #pragma unroll
        for (int nt = 0; nt < 8; nt++)
            #pragma unroll
            for (int rh = 0; rh < 2; rh++) {
                int rrow = wm * 32 + mti * 16 + g + rh * 8;
                int coll = wn * 64 + nt * 8 + 2 * tg;
                float v0 = acc[mti][nt][rh * 2 + 0] + __ldg(&bias[n0 * 128 + coll]);
                float v1 = acc[mti][nt][rh * 2 + 1] + __ldg(&bias[n0 * 128 + coll + 1]);
                *(__half2*)&stg[rrow * 128 + coll] = __floats2half2_rn(v0, v1);
            }
    __syncthreads();
    #pragma unroll
    for (int i = 0; i < 8; i++) {
        int unit = tid + i * 256;
        int rrow = unit >> 4, u = unit & 15;
        int m = m0 * 128 + rrow;
        int b = m / TT, t = m - b * TT;
        __half* dst = &out[((size_t)t * BB + b) * GG + n0 * 128];
        *(uint4*)((char*)dst + u * 16) = *(const uint4*)((char*)&stg[rrow * 128] + u * 16);
    }
}

// ---------------------------------------------------------------------------
// Persistent LSTM layer (fp16 operands, fp32 accum).
// 128 CTAs: m0 = blk & 7 (64 batch rows), j0 = blk >> 3 (48 hidden cols).
// 8 warps: wm(2) x wn(4); wn == gate. Warp tile 32m x 48n (6 n8-tiles).
// K-chunk 32 (2 x k16 blocks per stage), 3 stages, grid barrier per step.
// Stage = [A 1024 u32][B 3072 u32] = 16KB.
// dyn smem: stages 3*16384B | gsm 25088B | fs 6144B = 80384B
// ---------------------------------------------------------------------------
__global__ __launch_bounds__(256, 1) void lstm_persist(
    const uint32_t* __restrict__ Wf, const __half* __restrict__ xg,
    uint32_t* __restrict__ hfA, uint32_t* __restrict__ hfB,
    __half* __restrict__ hseq, int seq_all)
{
    extern __shared__ __align__(16) char smc[];
    float* gsm = (float*)(smc + 49152);
    __half* fsh = (__half*)(smc + 49152 + 25088);
    uint32_t* fsu = (uint32_t*)fsh;

    const int tid = threadIdx.x, lane = tid & 31, wid = tid >> 5;
    const int wm = wid >> 2, wn = wid & 3;
    const int m0 = blockIdx.x & 7, j0 = blockIdx.x >> 3;   // j0: 0..15
    const int g = lane >> 2, tg = lane & 3;
    const uint32_t* Bb = Wf + (size_t)j0 * (KC * 1536);

    float creg[2][8];
    #pragma unroll
    for (int p = 0; p < 2; p++)
        #pragma unroll
        for (int i = 0; i < 8; i++) creg[p][i] = 0.f;

    // epilogue thread mapping (192 active threads)
    const int ecj = tid % 48;
    const int er0 = tid / 48;     // 0..3 valid when tid < 192

    for (int t = 0; t < TT; t++) {
        const uint32_t* Ain = ((t & 1) ? hfB : hfA) + (size_t)m0 * (KC * 512);
        uint32_t* Hout = (t & 1) ? hfA : hfB;

        // chunk32 = 1024 u32 A + 3072 u32 B, contiguous in both sources
        auto cpAB = [&](int kcc) {
            uint32_t* dst = (uint32_t*)(smc + (kcc % 3) * 16384);
            cp16(&dst[tid * 4], Ain + (size_t)kcc * 1024 + tid * 4);
            const uint32_t* b = Bb + (size_t)kcc * 3072;
            #pragma unroll
            for (int i = 0; i < 3; i++)
                cp16(&dst[1024 + (tid + i * 256) * 4], b + (tid + i * 256) * 4);
        };

        float acc[2][6][4];
        #pragma unroll
        for (int i = 0; i < 2; i++)
            #pragma unroll
            for (int j = 0; j < 6; j++)
                #pragma unroll
                for (int k = 0; k < 4; k++) acc[i][j][k] = 0.f;

        cpAB(0); CPCOMMIT();
        cpAB(1); CPCOMMIT();

        for (int kcc = 0; kcc < NC32; kcc++) {
            if (kcc < NC32 - 1) CPW1(); else CPW0();
            __syncthreads();
            if (kcc + 2 < NC32) { cpAB(kcc + 2); CPCOMMIT(); }
            const uint32_t* stgb = (const uint32_t*)(smc + (kcc % 3) * 16384);
            #pragma unroll
            for (int half = 0; half < 2; half++) {
                const uint32_t* sA = stgb + half * 512;
                const uint32_t* sB = stgb + 1024 + half * 1536;
                uint4 af[2];
                #pragma unroll
                for (int mti = 0; mti < 2; mti++)
                    af[mti] = *(const uint4*)&sA[((2 * wm + mti) * 32 + lane) * 4];
                #pragma unroll
                for (int p = 0; p < 3; p++) {
                    uint4 bq = *(const uint4*)&sB[((wn * 3 + p) * 32 + lane) * 4];
                    mma16(acc[0][2 * p], af[0], bq.x, bq.y);
                    mma16(acc[1][2 * p], af[1], bq.x, bq.y);
                    mma16(acc[0][2 * p + 1], af[0], bq.z, bq.w);
                    mma16(acc[1][2 * p + 1], af[1], bq.z, bq.w);
                }
            }
        }

        // ---- epilogue: two 32-row passes through smem gate transpose ----
        for (int p = 0; p < 2; p++) {
            __syncthreads();
            if (wm == p) {
                #pragma unroll
                for (int mti = 0; mti < 2; mti++)
                    #pragma unroll
                    for (int nt = 0; nt < 6; nt++)
                        #pragma unroll
                        for (int r2 = 0; r2 < 4; r2++) {
                            int mi = mti * 16 + g + ((r2 & 2) ? 8 : 0);
                            int cj = nt * 8 + 2 * tg + (r2 & 1);
                            gsm[mi * 196 + wn * 49 + cj] = acc[mti][nt][r2];
                        }
            }
            __syncthreads();
            if (tid < 192) {
                #pragma unroll
                for (int i = 0; i < 8; i++) {
                    int r = er0 + 4 * i;
                    int bl = p * 32 + r;
                    int b = m0 * 64 + bl;
                    int j = j0 * 48 + ecj;
                    const __half* xh = xg + ((size_t)t * BB + b) * GG + j;
                    float pi = gsm[r * 196 + 0 * 49 + ecj] + __half2float(xh[0]);
                    float pf = gsm[r * 196 + 1 * 49 + ecj] + __half2float(xh[HH]);
                    float pg = gsm[r * 196 + 2 * 49 + ecj] + __half2float(xh[2 * HH]);
                    float po = gsm[r * 196 + 3 * 49 + ecj] + __half2float(xh[3 * HH]);
                    float iv = sig_ap(pi), fv = sig_ap(pf), gv = tanh_ap(pg), ov = sig_ap(po);
                    float cn = fv * creg[p][i] + iv * gv;
                    creg[p][i] = cn;
                    float hn = ov * tanh_ap(cn);
                    if (seq_all || t == TT - 1)
                        hseq[((size_t)b * TT + t) * HH + j] = __float2half(hn);
                    // stage h into fp16 A-frag layout (3 kc chunks: q = ecj/16)
                    int q = ecj >> 4, kl = ecj & 15;
                    int mt = bl >> 4, mloc = bl & 15;
                    int lf = (mloc & 7) * 4 + ((kl & 7) >> 1);
                    int reg = (kl >> 3) * 2 + (mloc >> 3);
                    fsh[((((q * 4 + mt) * 32 + lf) * 4) + reg) * 2 + (kl & 1)] =
                        __float2half(hn);
                }
            }
        }
        __syncthreads();
        if (t < TT - 1) {
            // coalesced frag store (1536 u32 = 384 uint4)
            size_t fb = ((size_t)m0 * KC + (size_t)j0 * 3) * 512;
            #pragma unroll
            for (int i = 0; i < 2; i++) {
                int e = tid + i * 256;
                if (e < 384)
                    *(uint4*)&Hout[fb + e * 4] = *(const uint4*)&fsu[e * 4];
            }
            __threadfence();
            __syncthreads();
            if (tid == 0) {
                atomicAdd(&g_bar, 1u);
                unsigned target = (unsigned)NCTA * (unsigned)(t + 1);
                while (true) {
                    unsigned v;
                    asm volatile("ld.global.acquire.gpu.u32 %0, [%1];"
                                 : "=r"(v) : "l"(&g_bar));
                    if (v >= target) break;
                    __nanosleep(16);
                }
            }
            __syncthreads();
        }
    }
}

// ---------------------------------------------------------------------------
// Projection + L2 normalize from hseq[:, T-1, :]
// ---------------------------------------------------------------------------
__global__ __launch_bounds__(256) void proj_kernel(
    const __half* __restrict__ hseq, const float* __restrict__ pw,
    const float* __restrict__ pb, float* __restrict__ out)
{
    __shared__ float hs[8][HH];
    __shared__ float red[256];
    const int b0 = blockIdx.x * 8;
    const int tid = threadIdx.x;

    for (int i = tid; i < 8 * HH; i += 256) {
        int r = i / HH, k = i % HH;
        hs[r][k] = __half2float(hseq[((size_t)(b0 + r) * TT + (TT - 1)) * HH + k]);
    }
    __syncthreads();

    float s[8];
    float bias = pb[tid];
    #pragma unroll
    for (int r = 0; r < 8; r++) s[r] = bias;
    const float* w = pw + (size_t)tid * HH;
    for (int k = 0; k < HH; k++) {
        float wv = w[k];
        #pragma unroll
        for (int r = 0; r < 8; r++) s[r] += wv * hs[r][k];
    }

    for (int r = 0; r < 8; r++) {
        red[tid] = s[r] * s[r];
        __syncthreads();
        for (int off = 128; off > 0; off >>= 1) {
            if (tid < off) red[tid] += red[tid + off];
            __syncthreads();
        }
        float rn = rsqrtf(red[0]);
        __syncthreads();
        out[(size_t)(b0 + r) * PR + tid] = s[r] * rn;
    }
}

// ---------------------------------------------------------------------------
// host
// ---------------------------------------------------------------------------
extern "C" void kernel_launch(void* const* d_in, const int* in_sizes, int n_in,
                              void* d_out, int out_size)
{
    const float* x = (const float*)d_in[0];
    const float* w_ih[3] = {(const float*)d_in[1], (const float*)d_in[5], (const float*)d_in[9]};
    const float* w_hh[3] = {(const float*)d_in[2], (const float*)d_in[6], (const float*)d_in[10]};
    const float* b_ih[3] = {(const float*)d_in[3], (const float*)d_in[7], (const float*)d_in[11]};
    const float* b_hh[3] = {(const float*)d_in[4], (const float*)d_in[8], (const float*)d_in[12]};
    const float* pw = (const float*)d_in[13];
    const float* pb = (const float*)d_in[14];
    float* out = (float*)d_out;

    cudaFuncSetAttribute(lstm_persist, cudaFuncAttributeMaxDynamicSharedMemorySize, 80384);
    cudaFuncSetAttribute(gemm_in3, cudaFuncAttributeMaxDynamicSharedMemorySize, 49152);

    __half *xg_p, *hs0_p, *hs1_p;
    uint32_t *hf_p, *whhf_p, *wihf_p;
    float *bias_p;
    cudaGetSymbolAddress((void**)&xg_p, g_xg);
    cudaGetSymbolAddress((void**)&hs0_p, g_hseq0);
    cudaGetSymbolAddress((void**)&hs1_p, g_hseq1);
    cudaGetSymbolAddress((void**)&hf_p, g_hfrag);
    cudaGetSymbolAddress((void**)&whhf_p, g_whhf);
    cudaGetSymbolAddress((void**)&wihf_p, g_wihf);
    cudaGetSymbolAddress((void**)&bias_p, g_bias);
    uint32_t* hf0 = hf_p;
    uint32_t* hf1 = hf_p + 196608;

    const __half* inH[3] = {nullptr, hs0_p, hs1_p};
    __half* outH[3] = {hs0_p, hs1_p, hs0_p};
    int Ks[3] = {NM, HH, HH};
    int Kcs[3] = {3, KC, KC};

    for (int l = 0; l < 3; l++) {
        int nW = GG * Kcs[l] * 16;
        frag_wih_kernel<<<(nW + 255) / 256, 256>>>(w_ih[l], (__half*)wihf_p, Ks[l], Kcs[l]);
        frag_whh_kernel<<<(GG * HH + 255) / 256, 256>>>(w_hh[l], (__half*)whhf_p);
        prep_bias<<<(GG + 255) / 256, 256>>>(b_ih[l], b_hh[l], bias_p);
        gemm_in3<<<dim3(GG / 128, (BB * TT) / 128), 256, 49152>>>(
            (l == 0) ? x : nullptr, inH[l], wihf_p, bias_p, xg_p, Ks[l], Kcs[l],
            (l == 0) ? 0 : 1);
        prep_state<<<(196608 + 255) / 256, 256>>>(hf0);
        lstm_persist<<<NCTA, 256, 80384>>>(whhf_p, xg_p, hf0, hf1, outH[l],
                                           (l < 2) ? 1 : 0);
    }
    proj_kernel<<<BB / 8, 256>>>(hs0_p, pw, pb, out);
}

// round 12
// speedup vs baseline: 5.7538x; 1.0011x over previous
#include <cuda_runtime.h>
#include <cuda_fp16.h>
#include <cstdint>
#include <math.h>

#define BB 512
#define TT 180
#define NM 40
#define HH 768
#define GG 3072   // 4*HH
#define PR 256
#define KC 48     // HH/16
#define NC64 12   // HH/64
#define NCTA 128  // 8 batch-tiles x 16 j-tiles

// lstm_persist dynamic smem layout (bytes)
#define SXG_OFF 98304      // stages: 3 x 32768
#define GSM_OFF 122880     // sxg: 24576
#define FS_OFF  147968     // gsm: 25088
#define LSTM_SMEM 154112   // fs: 6144

// ---- static device scratch ----
__device__ __half g_xg[(size_t)TT * BB * GG];        // [t][b][gcol] fp16
__device__ __half g_hseq0[(size_t)BB * TT * HH];
__device__ __half g_hseq1[(size_t)BB * TT * HH];
__device__ uint32_t g_hfrag[2 * 196608];             // A-frag fp16 h (ping-pong): [m0 8][kc 48][mt 4][lane 32][reg 4]
__device__ uint32_t g_whhf[1179648];                 // B-frag fp16 W_hh: [j0 16][kc 48][ntpair 12][lane 32][4]
__device__ uint32_t g_wihf[1179648];                 // B-frag fp16 W_ih: [n0 24][kc Kc][ntpair 8][lane 32][4]
__device__ float g_bias[GG];
__device__ unsigned g_bar;

__device__ __forceinline__ void mma16(float* d, uint4 a, uint32_t b0, uint32_t b1) {
    asm volatile(
        "mma.sync.aligned.m16n8k16.row.col.f32.f16.f16.f32 "
        "{%0,%1,%2,%3}, {%4,%5,%6,%7}, {%8,%9}, {%0,%1,%2,%3};\n"
        : "+f"(d[0]), "+f"(d[1]), "+f"(d[2]), "+f"(d[3])
        : "r"(a.x), "r"(a.y), "r"(a.z), "r"(a.w), "r"(b0), "r"(b1));
}

__device__ __forceinline__ void cp16(void* s, const void* g) {
    uint32_t sa = (uint32_t)__cvta_generic_to_shared(s);
    asm volatile("cp.async.cg.shared.global [%0], [%1], 16;\n" :: "r"(sa), "l"(g));
}
#define CPCOMMIT() asm volatile("cp.async.commit_group;\n")
#define CPW0() asm volatile("cp.async.wait_group 0;\n")
#define CPW1() asm volatile("cp.async.wait_group 1;\n")

__device__ __forceinline__ float tanh_ap(float x) {
    float y; asm("tanh.approx.f32 %0, %1;" : "=f"(y) : "f"(x)); return y;
}
__device__ __forceinline__ float sig_ap(float x) { return 0.5f * tanh_ap(0.5f * x) + 0.5f; }

__device__ __forceinline__ uint32_t packh2(float lo, float hi) {
    __half2 h = __floats2half2_rn(lo, hi);
    return *(uint32_t*)&h;
}

// ---------------------------------------------------------------------------
// Prepass: W_hh [GG][HH] -> fp16 B-frag [j0 16][kc 48][ntpair 12][lane 32][4 u32]
// j0 tiles of 48 hidden cols; ncol = gate*48 + cj (0..191).
// ---------------------------------------------------------------------------
__global__ void frag_whh_kernel(const float* __restrict__ W, __half* __restrict__ outh) {
    int idx = blockIdx.x * 256 + threadIdx.x;
    if (idx >= GG * HH) return;
    int r = idx / HH, k = idx - r * HH;
    int gate = r / HH;
    int jglob = r - gate * HH;
    int j0 = jglob / 48;
    int cj = jglob - j0 * 48;
    int ncol = gate * 48 + cj;               // 0..191
    int kc = k >> 4, kl = k & 15;
    int ntpair = ncol >> 4, sub = (ncol >> 3) & 1, nloc = ncol & 7;
    int lane = nloc * 4 + ((kl & 7) >> 1);
    int reg = kl >> 3;
    size_t u32i = ((((size_t)j0 * KC + kc) * 12 + ntpair) * 32 + lane) * 4 + sub * 2 + reg;
    outh[u32i * 2 + (kl & 1)] = __float2half(W[idx]);
}

// ---------------------------------------------------------------------------
// Prepass: W_ih [GG][K] -> fp16 B-frag [n0 24][kc Kc][ntpair 8][lane 32][4 u32]
// ---------------------------------------------------------------------------
__global__ void frag_wih_kernel(const float* __restrict__ W, __half* __restrict__ outh,
                                int K, int Kc) {
    int kb = Kc * 16;
    int idx = blockIdx.x * 256 + threadIdx.x;
    if (idx >= GG * kb) return;
    int r = idx / kb, k = idx - r * kb;
    int n0 = r >> 7, ncol = r & 127;
    int kc = k >> 4, kl = k & 15;
    int ntpair = ncol >> 4, sub = (ncol >> 3) & 1, nloc = ncol & 7;
    int lane = nloc * 4 + ((kl & 7) >> 1);
    int reg = kl >> 3;
    size_t u32i = ((((size_t)n0 * Kc + kc) * 8 + ntpair) * 32 + lane) * 4 + sub * 2 + reg;
    float v = (k < K) ? W[(size_t)r * K + k] : 0.f;
    outh[u32i * 2 + (kl & 1)] = __float2half(v);
}

// ---------------------------------------------------------------------------
__global__ void prep_bias(const float* __restrict__ bi, const float* __restrict__ bh,
                          float* __restrict__ bias) {
    int i = blockIdx.x * 256 + threadIdx.x;
    if (i < GG) bias[i] = bi[i] + bh[i];
}

__global__ void prep_state(uint32_t* __restrict__ hf) {
    int i = blockIdx.x * 256 + threadIdx.x;
    if (i == 0) g_bar = 0u;
    if (i < 196608) hf[i] = 0u;
}

// ---------------------------------------------------------------------------
// Input GEMM (unchanged — known good). CTA 128m x 128n, 8 warps.
// Dynamic smem: As 8192B | Bs 8192B | staging 32768B = 49152B
// ---------------------------------------------------------------------------
__global__ __launch_bounds__(256) void gemm_in3(
    const float* __restrict__ Af, const __half* __restrict__ Ah,
    const uint32_t* __restrict__ Bf, const float* __restrict__ bias,
    __half* __restrict__ out, int K, int Kc, int a_half)
{
    extern __shared__ __align__(16) char smd[];
    uint32_t (*As)[1024] = (uint32_t(*)[1024])smd;
    uint32_t (*Bs)[1024] = (uint32_t(*)[1024])(smd + 8192);
    __half* stg = (__half*)(smd + 16384);

    const int tid = threadIdx.x, lane = tid & 31, wid = tid >> 5;
    const int wm = wid >> 1, wn = wid & 1;
    const int n0 = blockIdx.x, m0 = blockIdx.y;
    const int g = lane >> 2, tg = lane & 3;

    float acc[2][8][4];
    #pragma unroll
    for (int i = 0; i < 2; i++)
        #pragma unroll
        for (int j = 0; j < 8; j++)
            #pragma unroll
            for (int k = 0; k < 4; k++) acc[i][j][k] = 0.f;

    const int row = tid >> 1, kp = (tid & 1) * 8;
    const int mt = row >> 4, mloc = row & 15;
    const int regbase = (kp >> 3) * 2 + (mloc >> 3);
    const uint32_t* Bbase = Bf + (size_t)n0 * Kc * 1024;

    uint32_t av[4];
    auto ldgA = [&](int kc) {
        int k0 = kc * 16;
        if (a_half) {
            const __half* src = Ah + (size_t)(m0 * 128 + row) * K + k0 + kp;
            uint4 v = *(const uint4*)src;
            av[0] = v.x; av[1] = v.y; av[2] = v.z; av[3] = v.w;
        } else {
            float t0[4] = {0, 0, 0, 0}, t1[4] = {0, 0, 0, 0};
            const float* src = Af + (size_t)(m0 * 128 + row) * K + k0 + kp;
            if (k0 + kp < K)     *(float4*)t0 = *(const float4*)src;
            if (k0 + kp + 4 < K) *(float4*)t1 = *(const float4*)(src + 4);
            av[0] = packh2(t0[0], t0[1]); av[1] = packh2(t0[2], t0[3]);
            av[2] = packh2(t1[0], t1[1]); av[3] = packh2(t1[2], t1[3]);
        }
    };
    auto stsA = [&](int buf) {
        #pragma unroll
        for (int i = 0; i < 4; i++)
            As[buf][(mt * 32 + (mloc & 7) * 4 + i) * 4 + regbase] = av[i];
    };
    auto cpB = [&](int buf, int kc) {
        const uint32_t* src = Bbase + (size_t)kc * 1024;
        cp16(&Bs[buf][tid * 4], src + tid * 4);
    };

    ldgA(0); cpB(0, 0); CPCOMMIT();
    stsA(0);
    CPW0();
    __syncthreads();

    for (int kc = 0; kc < Kc; kc++) {
        int cur = kc & 1, nxt = cur ^ 1;
        if (kc + 1 < Kc) { cpB(nxt, kc + 1); CPCOMMIT(); ldgA(kc + 1); }
        uint4 af[2];
        #pragma unroll
        for (int mti = 0; mti < 2; mti++)
            af[mti] = *(const uint4*)&As[cur][((2 * wm + mti) * 32 + lane) * 4];
        #pragma unroll
        for (int p = 0; p < 4; p++) {
            uint4 bq = *(const uint4*)&Bs[cur][((wn * 4 + p) * 32 + lane) * 4];
            mma16(acc[0][2 * p], af[0], bq.x, bq.y);
            mma16(acc[1][2 * p], af[1], bq.x, bq.y);
            mma16(acc[0][2 * p + 1], af[0], bq.z, bq.w);
            mma16(acc[1][2 * p + 1], af[1], bq.z, bq.w);
        }
        if (kc + 1 < Kc) { stsA(nxt); CPW0(); }
        __syncthreads();
    }

    #pragma unroll
    for (int mti = 0; mti < 2; mti++)
        #pragma unroll
        for (int nt = 0; nt < 8; nt++)
            #pragma unroll
            for (int rh = 0; rh < 2; rh++) {
                int rrow = wm * 32 + mti * 16 + g + rh * 8;
                int coll = wn * 64 + nt * 8 + 2 * tg;
                float v0 = acc[mti][nt][rh * 2 + 0] + __ldg(&bias[n0 * 128 + coll]);
                float v1 = acc[mti][nt][rh * 2 + 1] + __ldg(&bias[n0 * 128 + coll + 1]);
                *(__half2*)&stg[rrow * 128 + coll] = __floats2half2_rn(v0, v1);
            }
    __syncthreads();
    #pragma unroll
    for (int i = 0; i < 8; i++) {
        int unit = tid + i * 256;
        int rrow = unit >> 4, u = unit & 15;
        int m = m0 * 128 + rrow;
        int b = m / TT, t = m - b * TT;
        __half* dst = &out[((size_t)t * BB + b) * GG + n0 * 128];
        *(uint4*)((char*)dst + u * 16) = *(const uint4*)((char*)&stg[rrow * 128] + u * 16);
    }
}

// ---------------------------------------------------------------------------
// Persistent LSTM layer (fp16 operands, fp32 accum).
// 128 CTAs: m0 = blk & 7 (64 batch rows), j0 = blk >> 3 (48 hidden cols).
// 8 warps: wm(2) x wn(4). Warp tile 32m x 48n. K-chunk 64 (4 x k16 per stage),
// 3 stages, xg prefetched to smem each step, grid barrier per step.
// Stage = [A 2048 u32][B 6144 u32] = 32KB.
// ---------------------------------------------------------------------------
__global__ __launch_bounds__(256, 1) void lstm_persist(
    const uint32_t* __restrict__ Wf, const __half* __restrict__ xg,
    uint32_t* __restrict__ hfA, uint32_t* __restrict__ hfB,
    __half* __restrict__ hseq, int seq_all)
{
    extern __shared__ __align__(16) char smc[];
    __half* sxg = (__half*)(smc + SXG_OFF);     // [bl 64][gate 4][cj 48]
    float* gsm = (float*)(smc + GSM_OFF);
    __half* fsh = (__half*)(smc + FS_OFF);
    uint32_t* fsu = (uint32_t*)fsh;

    const int tid = threadIdx.x, lane = tid & 31, wid = tid >> 5;
    const int wm = wid >> 2, wn = wid & 3;
    const int m0 = blockIdx.x & 7, j0 = blockIdx.x >> 3;   // j0: 0..15
    const int g = lane >> 2, tg = lane & 3;
    const uint32_t* Bb = Wf + (size_t)j0 * (KC * 1536);

    float creg[2][8];
    #pragma unroll
    for (int p = 0; p < 2; p++)
        #pragma unroll
        for (int i = 0; i < 8; i++) creg[p][i] = 0.f;

    // epilogue thread mapping (192 active threads)
    const int ecj = tid % 48;
    const int er0 = tid / 48;     // 0..3 valid when tid < 192

    for (int t = 0; t < TT; t++) {
        const uint32_t* Ain = ((t & 1) ? hfB : hfA) + (size_t)m0 * (KC * 512);
        uint32_t* Hout = (t & 1) ? hfA : hfB;

        // chunk64 = 2048 u32 A + 6144 u32 B, contiguous in both sources
        auto cpAB = [&](int kcc) {
            uint32_t* dst = (uint32_t*)(smc + (kcc % 3) * 32768);
            const uint32_t* a = Ain + (size_t)kcc * 2048;
            cp16(&dst[tid * 4], a + tid * 4);
            cp16(&dst[(tid + 256) * 4], a + (tid + 256) * 4);
            const uint32_t* b = Bb + (size_t)kcc * 6144;
            #pragma unroll
            for (int i = 0; i < 6; i++)
                cp16(&dst[2048 + (tid + i * 256) * 4], b + (tid + i * 256) * 4);
        };
        // xg tile prefetch: 1536 uint4 = 64 rows x 4 gates x 6 (16B units)
        auto cpXG = [&]() {
            #pragma unroll
            for (int i = 0; i < 6; i++) {
                int u = tid + i * 256;
                int bl = u / 24, rem = u - bl * 24;
                int gate = rem / 6, s = rem - gate * 6;
                const __half* src = xg + ((size_t)t * BB + m0 * 64 + bl) * GG +
                                    gate * HH + j0 * 48 + s * 8;
                cp16(&sxg[(bl * 4 + gate) * 48 + s * 8], src);
            }
        };

        float acc[2][6][4];
        #pragma unroll
        for (int i = 0; i < 2; i++)
            #pragma unroll
            for (int j = 0; j < 6; j++)
                #pragma unroll
                for (int k = 0; k < 4; k++) acc[i][j][k] = 0.f;

        cpAB(0); cpXG(); CPCOMMIT();
        cpAB(1); CPCOMMIT();

        for (int kcc = 0; kcc < NC64; kcc++) {
            if (kcc < NC64 - 1) CPW1(); else CPW0();
            __syncthreads();
            if (kcc + 2 < NC64) { cpAB(kcc + 2); CPCOMMIT(); }
            const uint32_t* stgb = (const uint32_t*)(smc + (kcc % 3) * 32768);
            #pragma unroll
            for (int q = 0; q < 4; q++) {
                const uint32_t* sA = stgb + q * 512;
                const uint32_t* sB = stgb + 2048 + q * 1536;
                uint4 af[2];
                #pragma unroll
                for (int mti = 0; mti < 2; mti++)
                    af[mti] = *(const uint4*)&sA[((2 * wm + mti) * 32 + lane) * 4];
                #pragma unroll
                for (int p = 0; p < 3; p++) {
                    uint4 bq = *(const uint4*)&sB[((wn * 3 + p) * 32 + lane) * 4];
                    mma16(acc[0][2 * p], af[0], bq.x, bq.y);
                    mma16(acc[1][2 * p], af[1], bq.x, bq.y);
                    mma16(acc[0][2 * p + 1], af[0], bq.z, bq.w);
                    mma16(acc[1][2 * p + 1], af[1], bq.z, bq.w);
                }
            }
        }

        // ---- epilogue: two 32-row passes through smem gate transpose ----
        for (int p = 0; p < 2; p++) {
            __syncthreads();
            if (wm == p) {
                #pragma unroll
                for (int mti = 0; mti < 2; mti++)
                    #pragma unroll
                    for (int nt = 0; nt < 6; nt++)
                        #pragma unroll
                        for (int r2 = 0; r2 < 4; r2++) {
                            int mi = mti * 16 + g + ((r2 & 2) ? 8 : 0);
                            int cj = nt * 8 + 2 * tg + (r2 & 1);
                            gsm[mi * 196 + wn * 49 + cj] = acc[mti][nt][r2];
                        }
            }
            __syncthreads();
            if (tid < 192) {
                #pragma unroll
                for (int i = 0; i < 8; i++) {
                    int r = er0 + 4 * i;
                    int bl = p * 32 + r;
                    int b = m0 * 64 + bl;
                    int j = j0 * 48 + ecj;
                    const __half* xh = &sxg[bl * 192 + ecj];
                    float pi = gsm[r * 196 + 0 * 49 + ecj] + __half2float(xh[0]);
                    float pf = gsm[r * 196 + 1 * 49 + ecj] + __half2float(xh[48]);
                    float pg = gsm[r * 196 + 2 * 49 + ecj] + __half2float(xh[96]);
                    float po = gsm[r * 196 + 3 * 49 + ecj] + __half2float(xh[144]);
                    float iv = sig_ap(pi), fv = sig_ap(pf), gv = tanh_ap(pg), ov = sig_ap(po);
                    float cn = fv * creg[p][i] + iv * gv;
                    creg[p][i] = cn;
                    float hn = ov * tanh_ap(cn);
                    if (seq_all || t == TT - 1)
                        hseq[((size_t)b * TT + t) * HH + j] = __float2half(hn);
                    // stage h into fp16 A-frag layout (3 kc chunks: q = ecj/16)
                    int q = ecj >> 4, kl = ecj & 15;
                    int mt = bl >> 4, mloc = bl & 15;
                    int lf = (mloc & 7) * 4 + ((kl & 7) >> 1);
                    int reg = (kl >> 3) * 2 + (mloc >> 3);
                    fsh[((((q * 4 + mt) * 32 + lf) * 4) + reg) * 2 + (kl & 1)] =
                        __float2half(hn);
                }
            }
        }
        __syncthreads();
        if (t < TT - 1) {
            // coalesced frag store (1536 u32 = 384 uint4)
            size_t fb = ((size_t)m0 * KC + (size_t)j0 * 3) * 512;
            #pragma unroll
            for (int i = 0; i < 2; i++) {
                int e = tid + i * 256;
                if (e < 384)
                    *(uint4*)&Hout[fb + e * 4] = *(const uint4*)&fsu[e * 4];
            }
            __threadfence();
            __syncthreads();
            if (tid == 0) {
                atomicAdd(&g_bar, 1u);
                unsigned target = (unsigned)NCTA * (unsigned)(t + 1);
                while (true) {
                    unsigned v;
                    asm volatile("ld.global.acquire.gpu.u32 %0, [%1];"
                                 : "=r"(v) : "l"(&g_bar));
                    if (v >= target) break;
                    __nanosleep(16);
                }
            }
            __syncthreads();
        }
    }
}

// ---------------------------------------------------------------------------
// Projection + L2 normalize from hseq[:, T-1, :]
// ---------------------------------------------------------------------------
__global__ __launch_bounds__(256) void proj_kernel(
    const __half* __restrict__ hseq, const float* __restrict__ pw,
    const float* __restrict__ pb, float* __restrict__ out)
{
    __shared__ float hs[8][HH];
    __shared__ float red[256];
    const int b0 = blockIdx.x * 8;
    const int tid = threadIdx.x;

    for (int i = tid; i < 8 * HH; i += 256) {
        int r = i / HH, k = i % HH;
        hs[r][k] = __half2float(hseq[((size_t)(b0 + r) * TT + (TT - 1)) * HH + k]);
    }
    __syncthreads();

    float s[8];
    float bias = pb[tid];
    #pragma unroll
    for (int r = 0; r < 8; r++) s[r] = bias;
    const float* w = pw + (size_t)tid * HH;
    for (int k = 0; k < HH; k++) {
        float wv = w[k];
        #pragma unroll
        for (int r = 0; r < 8; r++) s[r] += wv * hs[r][k];
    }

    for (int r = 0; r < 8; r++) {
        red[tid] = s[r] * s[r];
        __syncthreads();
        for (int off = 128; off > 0; off >>= 1) {
            if (tid < off) red[tid] += red[tid + off];
            __syncthreads();
        }
        float rn = rsqrtf(red[0]);
        __syncthreads();
        out[(size_t)(b0 + r) * PR + tid] = s[r] * rn;
    }
}

// ---------------------------------------------------------------------------
// host
// ---------------------------------------------------------------------------
extern "C" void kernel_launch(void* const* d_in, const int* in_sizes, int n_in,
                              void* d_out, int out_size)
{
    const float* x = (const float*)d_in[0];
    const float* w_ih[3] = {(const float*)d_in[1], (const float*)d_in[5], (const float*)d_in[9]};
    const float* w_hh[3] = {(const float*)d_in[2], (const float*)d_in[6], (const float*)d_in[10]};
    const float* b_ih[3] = {(const float*)d_in[3], (const float*)d_in[7], (const float*)d_in[11]};
    const float* b_hh[3] = {(const float*)d_in[4], (const float*)d_in[8], (const float*)d_in[12]};
    const float* pw = (const float*)d_in[13];
    const float* pb = (const float*)d_in[14];
    float* out = (float*)d_out;

    cudaFuncSetAttribute(lstm_persist, cudaFuncAttributeMaxDynamicSharedMemorySize, LSTM_SMEM);
    cudaFuncSetAttribute(gemm_in3, cudaFuncAttributeMaxDynamicSharedMemorySize, 49152);

    __half *xg_p, *hs0_p, *hs1_p;
    uint32_t *hf_p, *whhf_p, *wihf_p;
    float *bias_p;
    cudaGetSymbolAddress((void**)&xg_p, g_xg);
    cudaGetSymbolAddress((void**)&hs0_p, g_hseq0);
    cudaGetSymbolAddress((void**)&hs1_p, g_hseq1);
    cudaGetSymbolAddress((void**)&hf_p, g_hfrag);
    cudaGetSymbolAddress((void**)&whhf_p, g_whhf);
    cudaGetSymbolAddress((void**)&wihf_p, g_wihf);
    cudaGetSymbolAddress((void**)&bias_p, g_bias);
    uint32_t* hf0 = hf_p;
    uint32_t* hf1 = hf_p + 196608;

    const __half* inH[3] = {nullptr, hs0_p, hs1_p};
    __half* outH[3] = {hs0_p, hs1_p, hs0_p};
    int Ks[3] = {NM, HH, HH};
    int Kcs[3] = {3, KC, KC};

    for (int l = 0; l < 3; l++) {
        int nW = GG * Kcs[l] * 16;
        frag_wih_kernel<<<(nW + 255) / 256, 256>>>(w_ih[l], (__half*)wihf_p, Ks[l], Kcs[l]);
        frag_whh_kernel<<<(GG * HH + 255) / 256, 256>>>(w_hh[l], (__half*)whhf_p);
        prep_bias<<<(GG + 255) / 256, 256>>>(b_ih[l], b_hh[l], bias_p);
        gemm_in3<<<dim3(GG / 128, (BB * TT) / 128), 256, 49152>>>(
            (l == 0) ? x : nullptr, inH[l], wihf_p, bias_p, xg_p, Ks[l], Kcs[l],
            (l == 0) ? 0 : 1);
        prep_state<<<(196608 + 255) / 256, 256>>>(hf0);
        lstm_persist<<<NCTA, 256, LSTM_SMEM>>>(whhf_p, xg_p, hf0, hf1, outH[l],
                                               (l < 2) ? 1 : 0);
    }
    proj_kernel<<<BB / 8, 256>>>(hs0_p, pw, pb, out);
}

// round 13
// speedup vs baseline: 5.8062x; 1.0091x over previous
#include <cuda_runtime.h>
#include <cuda_fp16.h>
#include <cstdint>
#include <math.h>

#define BB 512
#define TT 180
#define NM 40
#define HH 768
#define GG 3072   // 4*HH
#define PR 256
#define KC 48     // HH/16
#define NC64 12   // HH/64
#define NCTA 128  // 8 batch-tiles x 16 j-tiles

// lstm_persist dynamic smem layout (bytes)
#define SXG_OFF 98304      // stages: 3 x 32768
#define GSM_OFF 122880     // sxg: 24576
#define FS_OFF  147968     // gsm: 25088
#define LSTM_SMEM 154112   // fs: 6144

// ---- static device scratch ----
__device__ __half g_xg[(size_t)TT * BB * GG];        // [t][b][gcol] fp16
__device__ __half g_hseq0[(size_t)BB * TT * HH];
__device__ __half g_hseq1[(size_t)BB * TT * HH];
__device__ uint32_t g_hfrag[2 * 196608];             // A-frag fp16 h (ping-pong)
__device__ uint32_t g_whhf[1179648];                 // B-frag fp16 W_hh: [j0 16][kc 48][ntpair 12][lane 32][4]
__device__ uint32_t g_wihf[1179648];                 // B-frag fp16 W_ih: [n0 24][kc Kc][ntpair 8][lane 32][4]
__device__ float g_bias[GG];
__device__ unsigned g_bar;

__device__ __forceinline__ void mma16(float* d, uint4 a, uint32_t b0, uint32_t b1) {
    asm volatile(
        "mma.sync.aligned.m16n8k16.row.col.f32.f16.f16.f32 "
        "{%0,%1,%2,%3}, {%4,%5,%6,%7}, {%8,%9}, {%0,%1,%2,%3};\n"
        : "+f"(d[0]), "+f"(d[1]), "+f"(d[2]), "+f"(d[3])
        : "r"(a.x), "r"(a.y), "r"(a.z), "r"(a.w), "r"(b0), "r"(b1));
}

__device__ __forceinline__ void cp16(void* s, const void* g) {
    uint32_t sa = (uint32_t)__cvta_generic_to_shared(s);
    asm volatile("cp.async.cg.shared.global [%0], [%1], 16;\n" :: "r"(sa), "l"(g));
}
#define CPCOMMIT() asm volatile("cp.async.commit_group;\n")
#define CPW0() asm volatile("cp.async.wait_group 0;\n")
#define CPW1() asm volatile("cp.async.wait_group 1;\n")

__device__ __forceinline__ float tanh_ap(float x) {
    float y; asm("tanh.approx.f32 %0, %1;" : "=f"(y) : "f"(x)); return y;
}
__device__ __forceinline__ float sig_ap(float x) { return 0.5f * tanh_ap(0.5f * x) + 0.5f; }

__device__ __forceinline__ uint32_t packh2(float lo, float hi) {
    __half2 h = __floats2half2_rn(lo, hi);
    return *(uint32_t*)&h;
}

// ---------------------------------------------------------------------------
// prepA: both weight frag transforms in one launch.
//  W_hh -> [j0 16][kc 48][ntpair 12][lane 32][4]  (ncol = gate*48 + cj)
//  W_ih -> [n0 24][kc Kc][ntpair 8][lane 32][4]
// ---------------------------------------------------------------------------
__global__ void prepA_kernel(const float* __restrict__ Whh, __half* __restrict__ whhf,
                             const float* __restrict__ Wih, __half* __restrict__ wihf,
                             int K, int Kc) {
    int idx = blockIdx.x * 256 + threadIdx.x;
    if (idx < GG * HH) {
        int r = idx / HH, k = idx - r * HH;
        int gate = r / HH;
        int jglob = r - gate * HH;
        int j0 = jglob / 48;
        int cj = jglob - j0 * 48;
        int ncol = gate * 48 + cj;
        int kc = k >> 4, kl = k & 15;
        int ntpair = ncol >> 4, sub = (ncol >> 3) & 1, nloc = ncol & 7;
        int lane = nloc * 4 + ((kl & 7) >> 1);
        int reg = kl >> 3;
        size_t u32i = ((((size_t)j0 * KC + kc) * 12 + ntpair) * 32 + lane) * 4 + sub * 2 + reg;
        whhf[u32i * 2 + (kl & 1)] = __float2half(Whh[idx]);
    }
    int kb = Kc * 16;
    if (idx < GG * kb) {
        int r = idx / kb, k = idx - r * kb;
        int n0 = r >> 7, ncol = r & 127;
        int kc = k >> 4, kl = k & 15;
        int ntpair = ncol >> 4, sub = (ncol >> 3) & 1, nloc = ncol & 7;
        int lane = nloc * 4 + ((kl & 7) >> 1);
        int reg = kl >> 3;
        size_t u32i = ((((size_t)n0 * Kc + kc) * 8 + ntpair) * 32 + lane) * 4 + sub * 2 + reg;
        float v = (k < K) ? Wih[(size_t)r * K + k] : 0.f;
        wihf[u32i * 2 + (kl & 1)] = __float2half(v);
    }
}

// ---------------------------------------------------------------------------
// prepB: combined bias + zero h-frag + reset grid barrier
// ---------------------------------------------------------------------------
__global__ void prepB_kernel(const float* __restrict__ bi, const float* __restrict__ bh,
                             float* __restrict__ bias, uint32_t* __restrict__ hf) {
    int i = blockIdx.x * 256 + threadIdx.x;
    if (i == 0) g_bar = 0u;
    if (i < GG) bias[i] = bi[i] + bh[i];
    if (i < 196608) hf[i] = 0u;
}

// ---------------------------------------------------------------------------
// Input GEMM (unchanged — known good). CTA 128m x 128n, 8 warps.
// Dynamic smem: As 8192B | Bs 8192B | staging 32768B = 49152B
// ---------------------------------------------------------------------------
__global__ __launch_bounds__(256) void gemm_in3(
    const float* __restrict__ Af, const __half* __restrict__ Ah,
    const uint32_t* __restrict__ Bf, const float* __restrict__ bias,
    __half* __restrict__ out, int K, int Kc, int a_half)
{
    extern __shared__ __align__(16) char smd[];
    uint32_t (*As)[1024] = (uint32_t(*)[1024])smd;
    uint32_t (*Bs)[1024] = (uint32_t(*)[1024])(smd + 8192);
    __half* stg = (__half*)(smd + 16384);

    const int tid = threadIdx.x, lane = tid & 31, wid = tid >> 5;
    const int wm = wid >> 1, wn = wid & 1;
    const int n0 = blockIdx.x, m0 = blockIdx.y;
    const int g = lane >> 2, tg = lane & 3;

    float acc[2][8][4];
    #pragma unroll
    for (int i = 0; i < 2; i++)
        #pragma unroll
        for (int j = 0; j < 8; j++)
            #pragma unroll
            for (int k = 0; k < 4; k++) acc[i][j][k] = 0.f;

    const int row = tid >> 1, kp = (tid & 1) * 8;
    const int mt = row >> 4, mloc = row & 15;
    const int regbase = (kp >> 3) * 2 + (mloc >> 3);
    const uint32_t* Bbase = Bf + (size_t)n0 * Kc * 1024;

    uint32_t av[4];
    auto ldgA = [&](int kc) {
        int k0 = kc * 16;
        if (a_half) {
            const __half* src = Ah + (size_t)(m0 * 128 + row) * K + k0 + kp;
            uint4 v = *(const uint4*)src;
            av[0] = v.x; av[1] = v.y; av[2] = v.z; av[3] = v.w;
        } else {
            float t0[4] = {0, 0, 0, 0}, t1[4] = {0, 0, 0, 0};
            const float* src = Af + (size_t)(m0 * 128 + row) * K + k0 + kp;
            if (k0 + kp < K)     *(float4*)t0 = *(const float4*)src;
            if (k0 + kp + 4 < K) *(float4*)t1 = *(const float4*)(src + 4);
            av[0] = packh2(t0[0], t0[1]); av[1] = packh2(t0[2], t0[3]);
            av[2] = packh2(t1[0], t1[1]); av[3] = packh2(t1[2], t1[3]);
        }
    };
    auto stsA = [&](int buf) {
        #pragma unroll
        for (int i = 0; i < 4; i++)
            As[buf][(mt * 32 + (mloc & 7) * 4 + i) * 4 + regbase] = av[i];
    };
    auto cpB = [&](int buf, int kc) {
        const uint32_t* src = Bbase + (size_t)kc * 1024;
        cp16(&Bs[buf][tid * 4], src + tid * 4);
    };

    ldgA(0); cpB(0, 0); CPCOMMIT();
    stsA(0);
    CPW0();
    __syncthreads();

    for (int kc = 0; kc < Kc; kc++) {
        int cur = kc & 1, nxt = cur ^ 1;
        if (kc + 1 < Kc) { cpB(nxt, kc + 1); CPCOMMIT(); ldgA(kc + 1); }
        uint4 af[2];
        #pragma unroll
        for (int mti = 0; mti < 2; mti++)
            af[mti] = *(const uint4*)&As[cur][((2 * wm + mti) * 32 + lane) * 4];
        #pragma unroll
        for (int p = 0; p < 4; p++) {
            uint4 bq = *(const uint4*)&Bs[cur][((wn * 4 + p) * 32 + lane) * 4];
            mma16(acc[0][2 * p], af[0], bq.x, bq.y);
            mma16(acc[1][2 * p], af[1], bq.x, bq.y);
            mma16(acc[0][2 * p + 1], af[0], bq.z, bq.w);
            mma16(acc[1][2 * p + 1], af[1], bq.z, bq.w);
        }
        if (kc + 1 < Kc) { stsA(nxt); CPW0(); }
        __syncthreads();
    }

    #pragma unroll
    for (int mti = 0; mti < 2; mti++)
        #pragma unroll
        for (int nt = 0; nt < 8; nt++)
            #pragma unroll
            for (int rh = 0; rh < 2; rh++) {
                int rrow = wm * 32 + mti * 16 + g + rh * 8;
                int coll = wn * 64 + nt * 8 + 2 * tg;
                float v0 = acc[mti][nt][rh * 2 + 0] + __ldg(&bias[n0 * 128 + coll]);
                float v1 = acc[mti][nt][rh * 2 + 1] + __ldg(&bias[n0 * 128 + coll + 1]);
                *(__half2*)&stg[rrow * 128 + coll] = __floats2half2_rn(v0, v1);
            }
    __syncthreads();
    #pragma unroll
    for (int i = 0; i < 8; i++) {
        int unit = tid + i * 256;
        int rrow = unit >> 4, u = unit & 15;
        int m = m0 * 128 + rrow;
        int b = m / TT, t = m - b * TT;
        __half* dst = &out[((size_t)t * BB + b) * GG + n0 * 128];
        *(uint4*)((char*)dst + u * 16) = *(const uint4*)((char*)&stg[rrow * 128] + u * 16);
    }
}

// ---------------------------------------------------------------------------
// Persistent LSTM layer. 128 CTAs (8m x 16j), warp tile 32m x 48n.
// K-chunk 64, 3 stages. Step t+1's first two W-chunks + xg tile are
// prefetched BEFORE the grid barrier (barrier-independent); only A (h-frag)
// loads start after the barrier.
// ---------------------------------------------------------------------------
__global__ __launch_bounds__(256, 1) void lstm_persist(
    const uint32_t* __restrict__ Wf, const __half* __restrict__ xg,
    uint32_t* __restrict__ hfA, uint32_t* __restrict__ hfB,
    __half* __restrict__ hseq, int seq_all)
{
    extern __shared__ __align__(16) char smc[];
    __half* sxg = (__half*)(smc + SXG_OFF);     // [bl 64][gate 4][cj 48]
    float* gsm = (float*)(smc + GSM_OFF);
    __half* fsh = (__half*)(smc + FS_OFF);
    uint32_t* fsu = (uint32_t*)fsh;

    const int tid = threadIdx.x, lane = tid & 31, wid = tid >> 5;
    const int wm = wid >> 2, wn = wid & 3;
    const int m0 = blockIdx.x & 7, j0 = blockIdx.x >> 3;   // j0: 0..15
    const int g = lane >> 2, tg = lane & 3;
    const uint32_t* Bb = Wf + (size_t)j0 * (KC * 1536);

    float creg[2][8];
    #pragma unroll
    for (int p = 0; p < 2; p++)
        #pragma unroll
        for (int i = 0; i < 8; i++) creg[p][i] = 0.f;

    const int ecj = tid % 48;
    const int er0 = tid / 48;

    // B-part of a chunk64 stage (t-independent)
    auto cpB = [&](int kcc) {
        uint32_t* dst = (uint32_t*)(smc + (kcc % 3) * 32768);
        const uint32_t* b = Bb + (size_t)kcc * 6144;
        #pragma unroll
        for (int i = 0; i < 6; i++)
            cp16(&dst[2048 + (tid + i * 256) * 4], b + (tid + i * 256) * 4);
    };
    // xg tile prefetch for step tt
    auto cpXG = [&](int tt) {
        #pragma unroll
        for (int i = 0; i < 6; i++) {
            int u = tid + i * 256;
            int bl = u / 24, rem = u - bl * 24;
            int gate = rem / 6, s = rem - gate * 6;
            const __half* src = xg + ((size_t)tt * BB + m0 * 64 + bl) * GG +
                                gate * HH + j0 * 48 + s * 8;
            cp16(&sxg[(bl * 4 + gate) * 48 + s * 8], src);
        }
    };

    // initial P group for t = 0
    cpB(0); cpB(1); cpXG(0); CPCOMMIT();

    for (int t = 0; t < TT; t++) {
        const uint32_t* Ain = ((t & 1) ? hfB : hfA) + (size_t)m0 * (KC * 512);
        uint32_t* Hout = (t & 1) ? hfA : hfB;

        auto cpA = [&](int kcc) {
            uint32_t* dst = (uint32_t*)(smc + (kcc % 3) * 32768);
            const uint32_t* a = Ain + (size_t)kcc * 2048;
            cp16(&dst[tid * 4], a + tid * 4);
            cp16(&dst[(tid + 256) * 4], a + (tid + 256) * 4);
        };

        float acc[2][6][4];
        #pragma unroll
        for (int i = 0; i < 2; i++)
            #pragma unroll
            for (int j = 0; j < 6; j++)
                #pragma unroll
                for (int k = 0; k < 4; k++) acc[i][j][k] = 0.f;

        // post-barrier: only A loads are cold
        cpA(0); CPCOMMIT();
        cpA(1); CPCOMMIT();

        for (int kcc = 0; kcc < NC64; kcc++) {
            if (kcc < NC64 - 1) CPW1(); else CPW0();
            __syncthreads();
            if (kcc + 2 < NC64) { cpA(kcc + 2); cpB(kcc + 2); CPCOMMIT(); }
            const uint32_t* stgb = (const uint32_t*)(smc + (kcc % 3) * 32768);
            #pragma unroll
            for (int q = 0; q < 4; q++) {
                const uint32_t* sA = stgb + q * 512;
                const uint32_t* sB = stgb + 2048 + q * 1536;
                uint4 af[2];
                #pragma unroll
                for (int mti = 0; mti < 2; mti++)
                    af[mti] = *(const uint4*)&sA[((2 * wm + mti) * 32 + lane) * 4];
                #pragma unroll
                for (int p = 0; p < 3; p++) {
                    uint4 bq = *(const uint4*)&sB[((wn * 3 + p) * 32 + lane) * 4];
                    mma16(acc[0][2 * p], af[0], bq.x, bq.y);
                    mma16(acc[1][2 * p], af[1], bq.x, bq.y);
                    mma16(acc[0][2 * p + 1], af[0], bq.z, bq.w);
                    mma16(acc[1][2 * p + 1], af[1], bq.z, bq.w);
                }
            }
        }

        // ---- epilogue: two 32-row passes through smem gate transpose ----
        for (int p = 0; p < 2; p++) {
            __syncthreads();
            if (wm == p) {
                #pragma unroll
                for (int mti = 0; mti < 2; mti++)
                    #pragma unroll
                    for (int nt = 0; nt < 6; nt++)
                        #pragma unroll
                        for (int r2 = 0; r2 < 4; r2++) {
                            int mi = mti * 16 + g + ((r2 & 2) ? 8 : 0);
                            int cj = nt * 8 + 2 * tg + (r2 & 1);
                            gsm[mi * 196 + wn * 49 + cj] = acc[mti][nt][r2];
                        }
            }
            __syncthreads();
            if (tid < 192) {
                #pragma unroll
                for (int i = 0; i < 8; i++) {
                    int r = er0 + 4 * i;
                    int bl = p * 32 + r;
                    int b = m0 * 64 + bl;
                    int j = j0 * 48 + ecj;
                    const __half* xh = &sxg[bl * 192 + ecj];
                    float pi = gsm[r * 196 + 0 * 49 + ecj] + __half2float(xh[0]);
                    float pf = gsm[r * 196 + 1 * 49 + ecj] + __half2float(xh[48]);
                    float pg = gsm[r * 196 + 2 * 49 + ecj] + __half2float(xh[96]);
                    float po = gsm[r * 196 + 3 * 49 + ecj] + __half2float(xh[144]);
                    float iv = sig_ap(pi), fv = sig_ap(pf), gv = tanh_ap(pg), ov = sig_ap(po);
                    float cn = fv * creg[p][i] + iv * gv;
                    creg[p][i] = cn;
                    float hn = ov * tanh_ap(cn);
                    if (seq_all || t == TT - 1)
                        hseq[((size_t)b * TT + t) * HH + j] = __float2half(hn);
                    int q = ecj >> 4, kl = ecj & 15;
                    int mt = bl >> 4, mloc = bl & 15;
                    int lf = (mloc & 7) * 4 + ((kl & 7) >> 1);
                    int reg = (kl >> 3) * 2 + (mloc >> 3);
                    fsh[((((q * 4 + mt) * 32 + lf) * 4) + reg) * 2 + (kl & 1)] =
                        __float2half(hn);
                }
            }
        }
        __syncthreads();
        if (t < TT - 1) {
            // coalesced frag store (1536 u32 = 384 uint4)
            size_t fb = ((size_t)m0 * KC + (size_t)j0 * 3) * 512;
            #pragma unroll
            for (int i = 0; i < 2; i++) {
                int e = tid + i * 256;
                if (e < 384)
                    *(uint4*)&Hout[fb + e * 4] = *(const uint4*)&fsu[e * 4];
            }
            // prefetch next step's W chunks 0,1 + xg while waiting on the barrier
            cpB(0); cpB(1); cpXG(t + 1); CPCOMMIT();
            __threadfence();
            __syncthreads();
            if (tid == 0) {
                atomicAdd(&g_bar, 1u);
                unsigned target = (unsigned)NCTA * (unsigned)(t + 1);
                while (true) {
                    unsigned v;
                    asm volatile("ld.global.acquire.gpu.u32 %0, [%1];"
                                 : "=r"(v) : "l"(&g_bar));
                    if (v >= target) break;
                    __nanosleep(16);
                }
            }
            __syncthreads();
        }
    }
}

// ---------------------------------------------------------------------------
// Projection + L2 normalize from hseq[:, T-1, :]
// ---------------------------------------------------------------------------
__global__ __launch_bounds__(256) void proj_kernel(
    const __half* __restrict__ hseq, const float* __restrict__ pw,
    const float* __restrict__ pb, float* __restrict__ out)
{
    __shared__ float hs[8][HH];
    __shared__ float red[256];
    const int b0 = blockIdx.x * 8;
    const int tid = threadIdx.x;

    for (int i = tid; i < 8 * HH; i += 256) {
        int r = i / HH, k = i % HH;
        hs[r][k] = __half2float(hseq[((size_t)(b0 + r) * TT + (TT - 1)) * HH + k]);
    }
    __syncthreads();

    float s[8];
    float bias = pb[tid];
    #pragma unroll
    for (int r = 0; r < 8; r++) s[r] = bias;
    const float* w = pw + (size_t)tid * HH;
    for (int k = 0; k < HH; k++) {
        float wv = w[k];
        #pragma unroll
        for (int r = 0; r < 8; r++) s[r] += wv * hs[r][k];
    }

    for (int r = 0; r < 8; r++) {
        red[tid] = s[r] * s[r];
        __syncthreads();
        for (int off = 128; off > 0; off >>= 1) {
            if (tid < off) red[tid] += red[tid + off];
            __syncthreads();
        }
        float rn = rsqrtf(red[0]);
        __syncthreads();
        out[(size_t)(b0 + r) * PR + tid] = s[r] * rn;
    }
}

// ---------------------------------------------------------------------------
// host
// ---------------------------------------------------------------------------
extern "C" void kernel_launch(void* const* d_in, const int* in_sizes, int n_in,
                              void* d_out, int out_size)
{
    const float* x = (const float*)d_in[0];
    const float* w_ih[3] = {(const float*)d_in[1], (const float*)d_in[5], (const float*)d_in[9]};
    const float* w_hh[3] = {(const float*)d_in[2], (const float*)d_in[6], (const float*)d_in[10]};
    const float* b_ih[3] = {(const float*)d_in[3], (const float*)d_in[7], (const float*)d_in[11]};
    const float* b_hh[3] = {(const float*)d_in[4], (const float*)d_in[8], (const float*)d_in[12]};
    const float* pw = (const float*)d_in[13];
    const float* pb = (const float*)d_in[14];
    float* out = (float*)d_out;

    cudaFuncSetAttribute(lstm_persist, cudaFuncAttributeMaxDynamicSharedMemorySize, LSTM_SMEM);
    cudaFuncSetAttribute(gemm_in3, cudaFuncAttributeMaxDynamicSharedMemorySize, 49152);

    __half *xg_p, *hs0_p, *hs1_p;
    uint32_t *hf_p, *whhf_p, *wihf_p;
    float *bias_p;
    cudaGetSymbolAddress((void**)&xg_p, g_xg);
    cudaGetSymbolAddress((void**)&hs0_p, g_hseq0);
    cudaGetSymbolAddress((void**)&hs1_p, g_hseq1);
    cudaGetSymbolAddress((void**)&hf_p, g_hfrag);
    cudaGetSymbolAddress((void**)&whhf_p, g_whhf);
    cudaGetSymbolAddress((void**)&wihf_p, g_wihf);
    cudaGetSymbolAddress((void**)&bias_p, g_bias);
    uint32_t* hf0 = hf_p;
    uint32_t* hf1 = hf_p + 196608;

    const __half* inH[3] = {nullptr, hs0_p, hs1_p};
    __half* outH[3] = {hs0_p, hs1_p, hs0_p};
    int Ks[3] = {NM, HH, HH};
    int Kcs[3] = {3, KC, KC};

    for (int l = 0; l < 3; l++) {
        prepA_kernel<<<(GG * HH + 255) / 256, 256>>>(w_hh[l], (__half*)whhf_p,
                                                     w_ih[l], (__half*)wihf_p,
                                                     Ks[l], Kcs[l]);
        prepB_kernel<<<768, 256>>>(b_ih[l], b_hh[l], bias_p, hf0);
        gemm_in3<<<dim3(GG / 128, (BB * TT) / 128), 256, 49152>>>(
            (l == 0) ? x : nullptr, inH[l], wihf_p, bias_p, xg_p, Ks[l], Kcs[l],
            (l == 0) ? 0 : 1);
        lstm_persist<<<NCTA, 256, LSTM_SMEM>>>(whhf_p, xg_p, hf0, hf1, outH[l],
                                               (l < 2) ? 1 : 0);
    }
    proj_kernel<<<BB / 8, 256>>>(hs0_p, pw, pb, out);
}